// round 1
// baseline (speedup 1.0000x reference)
#include <cuda_runtime.h>
#include <cuda_bf16.h>
#include <math.h>

#define S_LEN 2048
#define D_MODEL 1024
#define N_HEADS 16
#define D_KV 64

// Scratch (allocation-free rule: __device__ globals)
__device__ float g_QKV[3 * N_HEADS * S_LEN * D_KV];   // [qkv][h][s][d]
__device__ float g_ctx[S_LEN * D_MODEL];              // [s][h*64+d]
__device__ float g_bias[N_HEADS * 4096];              // [h][delta + 2047]

// ---------------------------------------------------------------------------
// Bias LUT: bias[h][delta+2047] = rel_bias[bucket(delta)][h]
// ---------------------------------------------------------------------------
__global__ void bias_kernel(const float* __restrict__ rel_bias) {
    int idx = blockIdx.x * blockDim.x + threadIdx.x;
    if (idx >= N_HEADS * 4095) return;
    int h = idx / 4095;
    int di = idx % 4095;           // 0..4094
    int delta = di - 2047;         // k - q
    int bucket = (delta > 0) ? 16 : 0;
    int rp = abs(delta);
    if (rp < 8) {
        bucket += rp;
    } else {
        // mirror jnp float32 op order: (log(rp/8) / log(16)) * 8, trunc to int
        float lr = logf((float)rp * 0.125f) / 2.7725887f;
        int large = 8 + (int)(lr * 8.0f);
        bucket += (large < 15) ? large : 15;
    }
    g_bias[h * 4096 + di] = rel_bias[bucket * N_HEADS + h];
}

// ---------------------------------------------------------------------------
// Tiled SGEMM core: C[64x64] tile, BK=16, 256 threads, 4x4 micro-tile
// ---------------------------------------------------------------------------
__device__ __forceinline__ void gemm_tile(const float* __restrict__ A,
                                          const float* __restrict__ B,
                                          float acc[4][4],
                                          int K, int N, int m0, int n0) {
    __shared__ float As[16][64];
    __shared__ float Bs[16][64];
    int t = threadIdx.x;
    int tx = t & 15, ty = t >> 4;
    int ar = t >> 2, ac4 = (t & 3) * 4;
    int br = t >> 4, bc4 = (t & 15) * 4;

    for (int kb = 0; kb < K; kb += 16) {
        float4 av = *(const float4*)&A[(m0 + ar) * K + kb + ac4];
        As[ac4 + 0][ar] = av.x;
        As[ac4 + 1][ar] = av.y;
        As[ac4 + 2][ar] = av.z;
        As[ac4 + 3][ar] = av.w;
        *(float4*)&Bs[br][bc4] = *(const float4*)&B[(kb + br) * N + n0 + bc4];
        __syncthreads();
#pragma unroll
        for (int k = 0; k < 16; k++) {
            float4 a = *(float4*)&As[k][ty * 4];
            float4 b = *(float4*)&Bs[k][tx * 4];
            float ar4[4] = {a.x, a.y, a.z, a.w};
            float br4[4] = {b.x, b.y, b.z, b.w};
#pragma unroll
            for (int i = 0; i < 4; i++)
#pragma unroll
                for (int j = 0; j < 4; j++)
                    acc[i][j] = fmaf(ar4[i], br4[j], acc[i][j]);
        }
        __syncthreads();
    }
}

// QKV projection: z selects {Wq,Wk,Wv}; stores head-major [h][s][d]
__global__ void qkv_kernel(const float* __restrict__ X,
                           const float* __restrict__ Wq,
                           const float* __restrict__ Wk,
                           const float* __restrict__ Wv) {
    const float* W = (blockIdx.z == 0) ? Wq : (blockIdx.z == 1) ? Wk : Wv;
    float* Out = g_QKV + blockIdx.z * (N_HEADS * S_LEN * D_KV);
    int m0 = blockIdx.y * 64, n0 = blockIdx.x * 64;
    float acc[4][4] = {};
    gemm_tile(X, W, acc, D_MODEL, D_MODEL, m0, n0);
    int tx = threadIdx.x & 15, ty = threadIdx.x >> 4;
#pragma unroll
    for (int i = 0; i < 4; i++) {
#pragma unroll
        for (int j = 0; j < 4; j++) {
            int m = m0 + ty * 4 + i;
            int n = n0 + tx * 4 + j;
            Out[(n >> 6) * (S_LEN * D_KV) + m * D_KV + (n & 63)] = acc[i][j];
        }
    }
}

// Output projection: out = ctx @ Wo
__global__ void out_kernel(const float* __restrict__ Wo, float* __restrict__ out) {
    int m0 = blockIdx.y * 64, n0 = blockIdx.x * 64;
    float acc[4][4] = {};
    gemm_tile(g_ctx, Wo, acc, D_MODEL, D_MODEL, m0, n0);
    int tx = threadIdx.x & 15, ty = threadIdx.x >> 4;
#pragma unroll
    for (int i = 0; i < 4; i++)
#pragma unroll
        for (int j = 0; j < 4; j++)
            out[(m0 + ty * 4 + i) * D_MODEL + n0 + tx * 4 + j] = acc[i][j];
}

// ---------------------------------------------------------------------------
// Flash attention: 1 warp = 1 (head, q-row); 32-key tiles through smem
// ---------------------------------------------------------------------------
__global__ void attn_kernel() {
    int h = blockIdx.y;
    int q0 = blockIdx.x * 8;
    const float* Qg = g_QKV + 0 * (N_HEADS * S_LEN * D_KV) + h * S_LEN * D_KV;
    const float* Kg = g_QKV + 1 * (N_HEADS * S_LEN * D_KV) + h * S_LEN * D_KV;
    const float* Vg = g_QKV + 2 * (N_HEADS * S_LEN * D_KV) + h * S_LEN * D_KV;

    __shared__ float Qs[8][64];
    __shared__ float Ksh[64][33];   // [d][j], padded stride: conflict-free
    __shared__ float Vsh[32][64];   // [j][d]

    int t = threadIdx.x;
    int lane = t & 31;
    int w = t >> 5;

    for (int idx = t; idx < 8 * 64; idx += 256)
        Qs[idx >> 6][idx & 63] = Qg[(q0 + (idx >> 6)) * 64 + (idx & 63)];

    int q = q0 + w;
    const float* brow = g_bias + h * 4096 + (2047 - q);

    float m = -1e30f, l = 0.f, acc0 = 0.f, acc1 = 0.f;

    for (int k0 = 0; k0 < S_LEN; k0 += 32) {
        __syncthreads();
        for (int idx = t; idx < 32 * 64; idx += 256) {
            int j = idx >> 6, d = idx & 63;
            Ksh[d][j] = Kg[(k0 + j) * 64 + d];
            Vsh[j][d] = Vg[(k0 + j) * 64 + d];
        }
        __syncthreads();

        float s = 0.f;
#pragma unroll
        for (int d = 0; d < 64; d++)
            s = fmaf(Qs[w][d], Ksh[d][lane], s);
        s += __ldg(&brow[k0 + lane]);

        float tm = s;
#pragma unroll
        for (int o = 16; o; o >>= 1)
            tm = fmaxf(tm, __shfl_xor_sync(0xffffffffu, tm, o));
        float mn = fmaxf(m, tm);
        float c = __expf(m - mn);
        float p = __expf(s - mn);
        float ps = p;
#pragma unroll
        for (int o = 16; o; o >>= 1)
            ps += __shfl_xor_sync(0xffffffffu, ps, o);
        l = l * c + ps;
        acc0 *= c;
        acc1 *= c;
#pragma unroll
        for (int j = 0; j < 32; j++) {
            float pj = __shfl_sync(0xffffffffu, p, j);
            acc0 = fmaf(pj, Vsh[j][lane], acc0);
            acc1 = fmaf(pj, Vsh[j][lane + 32], acc1);
        }
        m = mn;
    }

    float inv = 1.f / l;
    g_ctx[q * D_MODEL + h * 64 + lane] = acc0 * inv;
    g_ctx[q * D_MODEL + h * 64 + lane + 32] = acc1 * inv;
}

// ---------------------------------------------------------------------------
extern "C" void kernel_launch(void* const* d_in, const int* in_sizes, int n_in,
                              void* d_out, int out_size) {
    const float* X   = (const float*)d_in[0];
    const float* Wq  = (const float*)d_in[1];
    const float* Wk  = (const float*)d_in[2];
    const float* Wv  = (const float*)d_in[3];
    const float* Wo  = (const float*)d_in[4];
    const float* rel = (const float*)d_in[5];
    float* out = (float*)d_out;

    bias_kernel<<<(N_HEADS * 4095 + 255) / 256, 256>>>(rel);
    qkv_kernel<<<dim3(D_MODEL / 64, S_LEN / 64, 3), 256>>>(X, Wq, Wk, Wv);
    attn_kernel<<<dim3(S_LEN / 8, N_HEADS), 256>>>();
    out_kernel<<<dim3(D_MODEL / 64, S_LEN / 64), 256>>>(Wo, out);
}

// round 2
// speedup vs baseline: 2.1492x; 2.1492x over previous
#include <cuda_runtime.h>
#include <math.h>

#define S_LEN 2048
#define D_MODEL 1024
#define N_HEADS 16
#define D_KV 64

// Scratch (allocation-free rule: __device__ globals)
__device__ float g_QKV[3 * N_HEADS * S_LEN * D_KV];   // [qkv][h][s][d]
__device__ float g_ctx[S_LEN * D_MODEL];              // [s][h*64+d]
__device__ float g_bias[N_HEADS * 4096];              // [h][delta + 2047]

// ---------------------------------------------------------------------------
// Bias LUT: bias[h][delta+2047] = rel_bias[bucket(delta)][h]
// ---------------------------------------------------------------------------
__global__ void bias_kernel(const float* __restrict__ rel_bias) {
    int idx = blockIdx.x * blockDim.x + threadIdx.x;
    if (idx >= N_HEADS * 4095) return;
    int h = idx / 4095;
    int di = idx % 4095;           // 0..4094
    int delta = di - 2047;         // k - q
    int bucket = (delta > 0) ? 16 : 0;
    int rp = abs(delta);
    if (rp < 8) {
        bucket += rp;
    } else {
        float lr = logf((float)rp * 0.125f) / 2.7725887f;
        int large = 8 + (int)(lr * 8.0f);
        bucket += (large < 15) ? large : 15;
    }
    g_bias[h * 4096 + di] = rel_bias[bucket * N_HEADS + h];
}

// ---------------------------------------------------------------------------
// SGEMM core: 128x128 tile, BK=8, 256 threads, 8x8 micro-tile (FMA-bound)
// ---------------------------------------------------------------------------
__device__ __forceinline__ void gemm_body(const float* __restrict__ A,
                                          const float* __restrict__ B,
                                          float acc[8][8], int m0, int n0) {
    __shared__ float As[8][128];
    __shared__ float Bs[8][128];
    const int t = threadIdx.x;
    const int tx = t & 15, ty = t >> 4;
    const int am = t >> 1;            // 0..127  (A row within tile)
    const int ak = (t & 1) * 4;       // 0 or 4  (A k within tile)
    const int bk = t >> 5;            // 0..7
    const int bn = (t & 31) * 4;      // 0..124

    for (int kb = 0; kb < D_MODEL; kb += 8) {
        float4 av = *(const float4*)&A[(m0 + am) * D_MODEL + kb + ak];
        float4 bv = *(const float4*)&B[(kb + bk) * D_MODEL + n0 + bn];
        __syncthreads();
        As[ak + 0][am] = av.x;
        As[ak + 1][am] = av.y;
        As[ak + 2][am] = av.z;
        As[ak + 3][am] = av.w;
        *(float4*)&Bs[bk][bn] = bv;
        __syncthreads();
#pragma unroll
        for (int k = 0; k < 8; k++) {
            float a[8], b[8];
            *(float4*)&a[0] = *(const float4*)&As[k][ty * 8];
            *(float4*)&a[4] = *(const float4*)&As[k][ty * 8 + 4];
            *(float4*)&b[0] = *(const float4*)&Bs[k][tx * 8];
            *(float4*)&b[4] = *(const float4*)&Bs[k][tx * 8 + 4];
#pragma unroll
            for (int i = 0; i < 8; i++)
#pragma unroll
                for (int j = 0; j < 8; j++)
                    acc[i][j] = fmaf(a[i], b[j], acc[i][j]);
        }
    }
}

// QKV projection: z selects {Wq,Wk,Wv}; stores head-major [h][s][d]
__global__ __launch_bounds__(256) void qkv_kernel(const float* __restrict__ X,
                                                  const float* __restrict__ Wq,
                                                  const float* __restrict__ Wk,
                                                  const float* __restrict__ Wv) {
    const float* W = (blockIdx.z == 0) ? Wq : (blockIdx.z == 1) ? Wk : Wv;
    float* Out = g_QKV + (size_t)blockIdx.z * (N_HEADS * S_LEN * D_KV);
    int m0 = blockIdx.y * 128, n0 = blockIdx.x * 128;
    float acc[8][8] = {};
    gemm_body(X, W, acc, m0, n0);
    const int tx = threadIdx.x & 15, ty = threadIdx.x >> 4;
    int n = n0 + tx * 8;
    int h = n >> 6, c = n & 63;
#pragma unroll
    for (int i = 0; i < 8; i++) {
        int m = m0 + ty * 8 + i;
        float* dst = Out + (size_t)h * (S_LEN * D_KV) + (size_t)m * D_KV + c;
        *(float4*)&dst[0] = make_float4(acc[i][0], acc[i][1], acc[i][2], acc[i][3]);
        *(float4*)&dst[4] = make_float4(acc[i][4], acc[i][5], acc[i][6], acc[i][7]);
    }
}

// Output projection: out = ctx @ Wo
__global__ __launch_bounds__(256) void out_kernel(const float* __restrict__ Wo,
                                                  float* __restrict__ out) {
    int m0 = blockIdx.y * 128, n0 = blockIdx.x * 128;
    float acc[8][8] = {};
    gemm_body(g_ctx, Wo, acc, m0, n0);
    const int tx = threadIdx.x & 15, ty = threadIdx.x >> 4;
#pragma unroll
    for (int i = 0; i < 8; i++) {
        int m = m0 + ty * 8 + i;
        float* dst = out + (size_t)m * D_MODEL + n0 + tx * 8;
        *(float4*)&dst[0] = make_float4(acc[i][0], acc[i][1], acc[i][2], acc[i][3]);
        *(float4*)&dst[4] = make_float4(acc[i][4], acc[i][5], acc[i][6], acc[i][7]);
    }
}

// ---------------------------------------------------------------------------
// Block-flash attention: CTA = (head, 64 q rows); 64-key tiles.
// S = Q@K^T and O += P@V as 4x4-microtile register GEMMs.
// Thread (ty,tx): q rows ty*4..+3, key cols / d cols tx*4..+3.
// ---------------------------------------------------------------------------
__global__ __launch_bounds__(256) void attn_kernel() {
    const int h = blockIdx.y;
    const int q0 = blockIdx.x * 64;
    const float* Qg = g_QKV + (size_t)h * (S_LEN * D_KV);
    const float* Kg = g_QKV + (size_t)(N_HEADS + h) * (S_LEN * D_KV);
    const float* Vg = g_QKV + (size_t)(2 * N_HEADS + h) * (S_LEN * D_KV);

    extern __shared__ float sm[];
    float (*Qt)[68]  = (float(*)[68])sm;               // [d][q]   (transposed Q)
    float (*KtP)[68] = (float(*)[68])(sm + 64 * 68);   // [d][k] then aliased as P[q][k]
    float (*Vs)[64]  = (float(*)[64])(sm + 2 * 64 * 68); // [k][d]

    const int t = threadIdx.x;
    const int tx = t & 15, ty = t >> 4;

    // Stage Q transposed (once)
    for (int idx = t; idx < 64 * 64; idx += 256) {
        int q = idx >> 6, d = idx & 63;
        Qt[d][q] = Qg[(q0 + q) * D_KV + d];
    }

    float m[4], l[4], o[4][4];
#pragma unroll
    for (int i = 0; i < 4; i++) {
        m[i] = -1e30f; l[i] = 0.f;
#pragma unroll
        for (int j = 0; j < 4; j++) o[i][j] = 0.f;
    }

    const float* bias_h = g_bias + h * 4096;

    for (int k0 = 0; k0 < S_LEN; k0 += 64) {
        __syncthreads();   // prior PV reads of Vs / P done
        // Stage K transposed + V
        for (int idx = t; idx < 64 * 64; idx += 256) {
            int kk = idx >> 6, d = idx & 63;
            KtP[d][kk] = Kg[(k0 + kk) * D_KV + d];
        }
        for (int idx = t; idx < 64 * 16; idx += 256) {
            int kk = idx >> 4, d4 = (idx & 15) * 4;
            *(float4*)&Vs[kk][d4] = *(const float4*)&Vg[(k0 + kk) * D_KV + d4];
        }
        __syncthreads();

        // S = Q @ K^T  (k-dim = d)
        float s[4][4] = {};
#pragma unroll
        for (int d = 0; d < 64; d++) {
            float4 a4 = *(const float4*)&Qt[d][ty * 4];
            float4 b4 = *(const float4*)&KtP[d][tx * 4];
            float a[4] = {a4.x, a4.y, a4.z, a4.w};
            float b[4] = {b4.x, b4.y, b4.z, b4.w};
#pragma unroll
            for (int i = 0; i < 4; i++)
#pragma unroll
                for (int j = 0; j < 4; j++)
                    s[i][j] = fmaf(a[i], b[j], s[i][j]);
        }

        // + bias
#pragma unroll
        for (int i = 0; i < 4; i++) {
            int q = q0 + ty * 4 + i;
            const float* br = bias_h + 2047 - q + k0 + tx * 4;
#pragma unroll
            for (int j = 0; j < 4; j++) s[i][j] += __ldg(&br[j]);
        }

        __syncthreads();   // all reads of Kt done; safe to alias as P

        // Online softmax per q row (row group = 16 lanes sharing ty)
#pragma unroll
        for (int i = 0; i < 4; i++) {
            float rm = fmaxf(fmaxf(s[i][0], s[i][1]), fmaxf(s[i][2], s[i][3]));
#pragma unroll
            for (int off = 8; off; off >>= 1)
                rm = fmaxf(rm, __shfl_xor_sync(0xffffffffu, rm, off));
            float mn = fmaxf(m[i], rm);
            float c = __expf(m[i] - mn);
            m[i] = mn;
            float rs = 0.f;
#pragma unroll
            for (int j = 0; j < 4; j++) {
                s[i][j] = __expf(s[i][j] - mn);
                rs += s[i][j];
            }
#pragma unroll
            for (int off = 8; off; off >>= 1)
                rs += __shfl_xor_sync(0xffffffffu, rs, off);
            l[i] = l[i] * c + rs;
#pragma unroll
            for (int j = 0; j < 4; j++) o[i][j] *= c;
            // Write P[q][k] into aliased buffer
            *(float4*)&KtP[ty * 4 + i][tx * 4] =
                make_float4(s[i][0], s[i][1], s[i][2], s[i][3]);
        }
        __syncthreads();

        // O += P @ V  (k-dim = key)
#pragma unroll
        for (int kk4 = 0; kk4 < 64; kk4 += 4) {
            float a[4][4];
#pragma unroll
            for (int i = 0; i < 4; i++)
                *(float4*)&a[i][0] = *(const float4*)&KtP[ty * 4 + i][kk4];
#pragma unroll
            for (int u = 0; u < 4; u++) {
                float4 b4 = *(const float4*)&Vs[kk4 + u][tx * 4];
                float b[4] = {b4.x, b4.y, b4.z, b4.w};
#pragma unroll
                for (int i = 0; i < 4; i++)
#pragma unroll
                    for (int j = 0; j < 4; j++)
                        o[i][j] = fmaf(a[i][u], b[j], o[i][j]);
            }
        }
    }

    // Epilogue: normalize, write ctx [s][h*64+d]
#pragma unroll
    for (int i = 0; i < 4; i++) {
        float inv = 1.f / l[i];
        int q = q0 + ty * 4 + i;
        *(float4*)&g_ctx[(size_t)q * D_MODEL + h * 64 + tx * 4] =
            make_float4(o[i][0] * inv, o[i][1] * inv, o[i][2] * inv, o[i][3] * inv);
    }
}

// ---------------------------------------------------------------------------
extern "C" void kernel_launch(void* const* d_in, const int* in_sizes, int n_in,
                              void* d_out, int out_size) {
    const float* X   = (const float*)d_in[0];
    const float* Wq  = (const float*)d_in[1];
    const float* Wk  = (const float*)d_in[2];
    const float* Wv  = (const float*)d_in[3];
    const float* Wo  = (const float*)d_in[4];
    const float* rel = (const float*)d_in[5];
    float* out = (float*)d_out;

    const int attn_smem = (2 * 64 * 68 + 64 * 64) * sizeof(float);  // 51200 B
    cudaFuncSetAttribute(attn_kernel,
                         cudaFuncAttributeMaxDynamicSharedMemorySize, attn_smem);

    bias_kernel<<<(N_HEADS * 4095 + 255) / 256, 256>>>(rel);
    qkv_kernel<<<dim3(D_MODEL / 128, S_LEN / 128, 3), 256>>>(X, Wq, Wk, Wv);
    attn_kernel<<<dim3(S_LEN / 64, N_HEADS), 256, attn_smem>>>();
    out_kernel<<<dim3(D_MODEL / 128, S_LEN / 128), 256>>>(Wo, out);
}

// round 4
// speedup vs baseline: 3.1510x; 1.4661x over previous
#include <cuda_runtime.h>
#include <cuda_bf16.h>
#include <math.h>
#include <cstdint>

#define S_LEN 2048
#define D_MODEL 1024
#define N_HEADS 16
#define D_KV 64

// ---------------- scratch (__device__ globals; no allocs) -------------------
__device__ float g_QKV[3 * N_HEADS * S_LEN * D_KV];   // [z][h][s][d]
__device__ float g_ctx[S_LEN * D_MODEL];              // [s][h*64+d]
__device__ float g_bias[N_HEADS * 4096];              // [h][delta+2047]
__device__ __align__(16) __nv_bfloat16 g_Ah[S_LEN * D_MODEL];   // A hi (X, then ctx)
__device__ __align__(16) __nv_bfloat16 g_Al[S_LEN * D_MODEL];   // A lo
__device__ __align__(16) __nv_bfloat16 g_Bh[4096 * D_MODEL];    // W^T hi (rows: 0..3071 qkv, 3072.. Wo)
__device__ __align__(16) __nv_bfloat16 g_Bl[4096 * D_MODEL];    // W^T lo

__device__ __forceinline__ uint32_t smem_u32(const void* p) {
    uint32_t a;
    asm("{ .reg .u64 t; cvta.to.shared.u64 t, %1; cvt.u32.u64 %0, t; }" : "=r"(a) : "l"(p));
    return a;
}

// ---------------------------------------------------------------------------
// Bias LUT
// ---------------------------------------------------------------------------
__global__ void bias_kernel(const float* __restrict__ rel_bias) {
    int idx = blockIdx.x * blockDim.x + threadIdx.x;
    if (idx >= N_HEADS * 4095) return;
    int h = idx / 4095;
    int di = idx % 4095;
    int delta = di - 2047;
    int bucket = (delta > 0) ? 16 : 0;
    int rp = abs(delta);
    if (rp < 8) {
        bucket += rp;
    } else {
        float lr = logf((float)rp * 0.125f) / 2.7725887f;
        int large = 8 + (int)(lr * 8.0f);
        bucket += (large < 15) ? large : 15;
    }
    g_bias[h * 4096 + di] = rel_bias[bucket * N_HEADS + h];
}

// ---------------------------------------------------------------------------
// fp32 -> bf16 hi/lo split converters
// ---------------------------------------------------------------------------
__device__ __forceinline__ void split_store(const float4 v, __nv_bfloat16* dh, __nv_bfloat16* dl) {
    float x[4] = {v.x, v.y, v.z, v.w};
    __nv_bfloat162 h2[2], l2[2];
#pragma unroll
    for (int i = 0; i < 2; i++) {
        __nv_bfloat16 h0 = __float2bfloat16_rn(x[2 * i]);
        __nv_bfloat16 h1 = __float2bfloat16_rn(x[2 * i + 1]);
        h2[i].x = h0; h2[i].y = h1;
        l2[i].x = __float2bfloat16_rn(x[2 * i] - __bfloat162float(h0));
        l2[i].y = __float2bfloat16_rn(x[2 * i + 1] - __bfloat162float(h1));
    }
    *(__nv_bfloat162*)(dh + 0) = h2[0];
    *(__nv_bfloat162*)(dh + 2) = h2[1];
    *(__nv_bfloat162*)(dl + 0) = l2[0];
    *(__nv_bfloat162*)(dl + 2) = l2[1];
}

__global__ void convA_kernel(const float* __restrict__ X) {
    int i = (blockIdx.x * blockDim.x + threadIdx.x) * 4;
    split_store(*(const float4*)(X + i), g_Ah + i, g_Al + i);
}

__global__ void convCtx_kernel() {
    int i = (blockIdx.x * blockDim.x + threadIdx.x) * 4;
    split_store(*(const float4*)(g_ctx + i), g_Ah + i, g_Al + i);
}

// Transpose + split W's into g_Bh/g_Bl rows [n][k]; z: 0=Wq 1=Wk 2=Wv 3=Wo
__global__ void convB_kernel(const float* __restrict__ Wq, const float* __restrict__ Wk,
                             const float* __restrict__ Wv, const float* __restrict__ Wo) {
    const float* W = (blockIdx.z == 0) ? Wq : (blockIdx.z == 1) ? Wk
                   : (blockIdx.z == 2) ? Wv : Wo;
    __shared__ float sm[32][33];
    int n0 = blockIdx.x * 32, k0 = blockIdx.y * 32;
    int tx = threadIdx.x, ty = threadIdx.y;   // 32 x 8
#pragma unroll
    for (int j = 0; j < 4; j++)
        sm[ty + j * 8][tx] = W[(size_t)(k0 + ty + j * 8) * D_MODEL + n0 + tx];
    __syncthreads();
#pragma unroll
    for (int j = 0; j < 4; j++) {
        int n = n0 + ty + j * 8, k = k0 + tx;
        float v = sm[tx][ty + j * 8];
        __nv_bfloat16 h = __float2bfloat16_rn(v);
        size_t o = (size_t)(blockIdx.z * 1024 + n) * D_MODEL + k;
        g_Bh[o] = h;
        g_Bl[o] = __float2bfloat16_rn(v - __bfloat162float(h));
    }
}

// ---------------------------------------------------------------------------
// mma.sync bf16 GEMM (3-term hi/lo split), C = A[2048xK] @ B^T (B rows = out cols)
// CTA tile 128x128, BK=64, cp.async double-buffered. Warp grid 4(M) x 2(N),
// warp tile 32x64: 2 m16 x 8 n8 mma tiles, 3 mma per tile per k16.
// ---------------------------------------------------------------------------
#define PITCH 72                       // bf16 elems per smem row (64 + 8 pad)
#define TILE_E (128 * PITCH)           // 9216 bf16 per array
#define STAGE_E (4 * TILE_E)           // Ah,Al,Bh,Bl
// dynamic smem: 2 stages * STAGE_E * 2B = 147456 bytes

__device__ __forceinline__ void ldm_x4(uint32_t* r, uint32_t addr) {
    asm volatile("ldmatrix.sync.aligned.m8n8.x4.shared.b16 {%0,%1,%2,%3}, [%4];"
                 : "=r"(r[0]), "=r"(r[1]), "=r"(r[2]), "=r"(r[3]) : "r"(addr));
}
__device__ __forceinline__ void ldm_x2(uint32_t* r, uint32_t addr) {
    asm volatile("ldmatrix.sync.aligned.m8n8.x2.shared.b16 {%0,%1}, [%2];"
                 : "=r"(r[0]), "=r"(r[1]) : "r"(addr));
}
__device__ __forceinline__ void mma16816(float* d, const uint32_t* a, const uint32_t* b) {
    asm volatile("mma.sync.aligned.m16n8k16.row.col.f32.bf16.bf16.f32 "
                 "{%0,%1,%2,%3}, {%4,%5,%6,%7}, {%8,%9}, {%0,%1,%2,%3};"
                 : "+f"(d[0]), "+f"(d[1]), "+f"(d[2]), "+f"(d[3])
                 : "r"(a[0]), "r"(a[1]), "r"(a[2]), "r"(a[3]), "r"(b[0]), "r"(b[1]));
}
__device__ __forceinline__ void cp16(uint32_t saddr, const void* gaddr) {
    asm volatile("cp.async.cg.shared.global [%0], [%1], 16;" :: "r"(saddr), "l"(gaddr));
}

template <bool QKV>
__global__ __launch_bounds__(256) void gemm_mma(float* __restrict__ Cout) {
    extern __shared__ __align__(16) __nv_bfloat16 sm[];
    const int t = threadIdx.x;
    const int warp = t >> 5, lane = t & 31;
    const int m0 = blockIdx.y * 128, n0 = blockIdx.x * 128;
    const int wm0 = (warp >> 1) * 32;   // warp M offset in tile
    const int wn0 = (warp & 1) * 64;    // warp N offset in tile

    const __nv_bfloat16* Bh = g_Bh + (QKV ? 0 : (size_t)3072 * D_MODEL);
    const __nv_bfloat16* Bl = g_Bl + (QKV ? 0 : (size_t)3072 * D_MODEL);

    const uint32_t sbase = smem_u32(sm);

    // cp.async loader mapping: 4 chunks/thread/array; chunk = 16B (8 bf16)
    const int lrow[4] = { (t + 0) >> 3, (t + 256) >> 3, (t + 512) >> 3, (t + 768) >> 3 };
    const int lcol = (t & 7) * 8;

    auto issue_stage = [&](int stage, int kb) {
        uint32_t so = sbase + (uint32_t)stage * STAGE_E * 2;
#pragma unroll
        for (int p = 0; p < 4; p++) {
            int row = lrow[p];
            uint32_t sofs = ((uint32_t)row * PITCH + lcol) * 2;
            size_t ga = (size_t)(m0 + row) * D_MODEL + kb * 64 + lcol;
            size_t gb = (size_t)(n0 + row) * D_MODEL + kb * 64 + lcol;
            cp16(so + sofs,                  g_Ah + ga);
            cp16(so + TILE_E * 2 + sofs,     g_Al + ga);
            cp16(so + TILE_E * 4 + sofs,     Bh + gb);
            cp16(so + TILE_E * 6 + sofs,     Bl + gb);
        }
        asm volatile("cp.async.commit_group;" ::: "memory");
    };

    float d[2][8][4];
#pragma unroll
    for (int i = 0; i < 2; i++)
#pragma unroll
        for (int j = 0; j < 8; j++)
#pragma unroll
            for (int u = 0; u < 4; u++) d[i][j][u] = 0.f;

    // fragment smem addresses (byte offsets within a stage)
    const int arow = wm0 + (lane & 15);
    const int acolq = (lane >> 4) * 8;          // 0 or 8 within k16
    const int brow = wn0 + (lane & 7);
    const int bcolq = ((lane >> 3) & 1) * 8;

    issue_stage(0, 0);

    for (int kb = 0; kb < 16; kb++) {
        if (kb + 1 < 16) {
            issue_stage((kb + 1) & 1, kb + 1);
            asm volatile("cp.async.wait_group 1;" ::: "memory");
        } else {
            asm volatile("cp.async.wait_group 0;" ::: "memory");
        }
        __syncthreads();

        uint32_t so = sbase + (uint32_t)(kb & 1) * STAGE_E * 2;
#pragma unroll
        for (int ks = 0; ks < 4; ks++) {
            uint32_t ah[2][4], al[2][4];
#pragma unroll
            for (int i = 0; i < 2; i++) {
                uint32_t aofs = ((uint32_t)(arow + i * 16) * PITCH + ks * 16 + acolq) * 2;
                ldm_x4(ah[i], so + aofs);
                ldm_x4(al[i], so + TILE_E * 2 + aofs);
            }
#pragma unroll
            for (int j = 0; j < 8; j++) {
                uint32_t bofs = ((uint32_t)(brow + j * 8) * PITCH + ks * 16 + bcolq) * 2;
                uint32_t bh[2], bl[2];
                ldm_x2(bh, so + TILE_E * 4 + bofs);
                ldm_x2(bl, so + TILE_E * 6 + bofs);
#pragma unroll
                for (int i = 0; i < 2; i++) {
                    mma16816(d[i][j], ah[i], bh);
                    mma16816(d[i][j], ah[i], bl);
                    mma16816(d[i][j], al[i], bh);
                }
            }
        }
        __syncthreads();
    }

    // epilogue
#pragma unroll
    for (int i = 0; i < 2; i++) {
        int r = m0 + wm0 + i * 16 + (lane >> 2);
#pragma unroll
        for (int j = 0; j < 8; j++) {
            int n = n0 + wn0 + j * 8 + (lane & 3) * 2;
            float* dst0;
            float* dst1;
            if (QKV) {
                int z = n >> 10, h = (n >> 6) & 15, dd = n & 63;
                float* base = g_QKV + ((size_t)z * N_HEADS + h) * (S_LEN * D_KV) + dd;
                dst0 = base + (size_t)r * D_KV;
                dst1 = base + (size_t)(r + 8) * D_KV;
            } else {
                dst0 = Cout + (size_t)r * D_MODEL + n;
                dst1 = Cout + (size_t)(r + 8) * D_MODEL + n;
            }
            *(float2*)dst0 = make_float2(d[i][j][0], d[i][j][1]);
            *(float2*)dst1 = make_float2(d[i][j][2], d[i][j][3]);
        }
    }
}

// ---------------------------------------------------------------------------
// Block-flash attention (unchanged from R2; fp32 SIMT)
// ---------------------------------------------------------------------------
__global__ __launch_bounds__(256) void attn_kernel() {
    const int h = blockIdx.y;
    const int q0 = blockIdx.x * 64;
    const float* Qg = g_QKV + (size_t)h * (S_LEN * D_KV);
    const float* Kg = g_QKV + (size_t)(N_HEADS + h) * (S_LEN * D_KV);
    const float* Vg = g_QKV + (size_t)(2 * N_HEADS + h) * (S_LEN * D_KV);

    extern __shared__ float smf[];
    float (*Qt)[68]  = (float(*)[68])smf;
    float (*KtP)[68] = (float(*)[68])(smf + 64 * 68);
    float (*Vs)[64]  = (float(*)[64])(smf + 2 * 64 * 68);

    const int t = threadIdx.x;
    const int tx = t & 15, ty = t >> 4;

    for (int idx = t; idx < 64 * 64; idx += 256) {
        int q = idx >> 6, d = idx & 63;
        Qt[d][q] = Qg[(q0 + q) * D_KV + d];
    }

    float m[4], l[4], o[4][4];
#pragma unroll
    for (int i = 0; i < 4; i++) {
        m[i] = -1e30f; l[i] = 0.f;
#pragma unroll
        for (int j = 0; j < 4; j++) o[i][j] = 0.f;
    }

    const float* bias_h = g_bias + h * 4096;

    for (int k0 = 0; k0 < S_LEN; k0 += 64) {
        __syncthreads();
        for (int idx = t; idx < 64 * 64; idx += 256) {
            int kk = idx >> 6, d = idx & 63;
            KtP[d][kk] = Kg[(k0 + kk) * D_KV + d];
        }
        for (int idx = t; idx < 64 * 16; idx += 256) {
            int kk = idx >> 4, d4 = (idx & 15) * 4;
            *(float4*)&Vs[kk][d4] = *(const float4*)&Vg[(k0 + kk) * D_KV + d4];
        }
        __syncthreads();

        float s[4][4] = {};
#pragma unroll
        for (int d = 0; d < 64; d++) {
            float4 a4 = *(const float4*)&Qt[d][ty * 4];
            float4 b4 = *(const float4*)&KtP[d][tx * 4];
            float a[4] = {a4.x, a4.y, a4.z, a4.w};
            float b[4] = {b4.x, b4.y, b4.z, b4.w};
#pragma unroll
            for (int i = 0; i < 4; i++)
#pragma unroll
                for (int j = 0; j < 4; j++)
                    s[i][j] = fmaf(a[i], b[j], s[i][j]);
        }

#pragma unroll
        for (int i = 0; i < 4; i++) {
            int q = q0 + ty * 4 + i;
            const float* br = bias_h + 2047 - q + k0 + tx * 4;
#pragma unroll
            for (int j = 0; j < 4; j++) s[i][j] += __ldg(&br[j]);
        }

        __syncthreads();

#pragma unroll
        for (int i = 0; i < 4; i++) {
            float rm = fmaxf(fmaxf(s[i][0], s[i][1]), fmaxf(s[i][2], s[i][3]));
#pragma unroll
            for (int off = 8; off; off >>= 1)
                rm = fmaxf(rm, __shfl_xor_sync(0xffffffffu, rm, off));
            float mn = fmaxf(m[i], rm);
            float cc = __expf(m[i] - mn);
            m[i] = mn;
            float rs = 0.f;
#pragma unroll
            for (int j = 0; j < 4; j++) {
                s[i][j] = __expf(s[i][j] - mn);
                rs += s[i][j];
            }
#pragma unroll
            for (int off = 8; off; off >>= 1)
                rs += __shfl_xor_sync(0xffffffffu, rs, off);
            l[i] = l[i] * cc + rs;
#pragma unroll
            for (int j = 0; j < 4; j++) o[i][j] *= cc;
            *(float4*)&KtP[ty * 4 + i][tx * 4] =
                make_float4(s[i][0], s[i][1], s[i][2], s[i][3]);
        }
        __syncthreads();

#pragma unroll
        for (int kk4 = 0; kk4 < 64; kk4 += 4) {
            float a[4][4];
#pragma unroll
            for (int i = 0; i < 4; i++)
                *(float4*)&a[i][0] = *(const float4*)&KtP[ty * 4 + i][kk4];
#pragma unroll
            for (int u = 0; u < 4; u++) {
                float4 b4 = *(const float4*)&Vs[kk4 + u][tx * 4];
                float b[4] = {b4.x, b4.y, b4.z, b4.w};
#pragma unroll
                for (int i = 0; i < 4; i++)
#pragma unroll
                    for (int j = 0; j < 4; j++)
                        o[i][j] = fmaf(a[i][u], b[j], o[i][j]);
            }
        }
    }

#pragma unroll
    for (int i = 0; i < 4; i++) {
        float inv = 1.f / l[i];
        int q = q0 + ty * 4 + i;
        *(float4*)&g_ctx[(size_t)q * D_MODEL + h * 64 + tx * 4] =
            make_float4(o[i][0] * inv, o[i][1] * inv, o[i][2] * inv, o[i][3] * inv);
    }
}

// ---------------------------------------------------------------------------
extern "C" void kernel_launch(void* const* d_in, const int* in_sizes, int n_in,
                              void* d_out, int out_size) {
    const float* X   = (const float*)d_in[0];
    const float* Wq  = (const float*)d_in[1];
    const float* Wk  = (const float*)d_in[2];
    const float* Wv  = (const float*)d_in[3];
    const float* Wo  = (const float*)d_in[4];
    const float* rel = (const float*)d_in[5];
    float* out = (float*)d_out;

    const int gemm_smem = 2 * STAGE_E * 2;   // 147456 bytes
    const int attn_smem = (2 * 64 * 68 + 64 * 64) * sizeof(float);
    cudaFuncSetAttribute(gemm_mma<true>,  cudaFuncAttributeMaxDynamicSharedMemorySize, gemm_smem);
    cudaFuncSetAttribute(gemm_mma<false>, cudaFuncAttributeMaxDynamicSharedMemorySize, gemm_smem);
    cudaFuncSetAttribute(attn_kernel,     cudaFuncAttributeMaxDynamicSharedMemorySize, attn_smem);

    bias_kernel<<<(N_HEADS * 4095 + 255) / 256, 256>>>(rel);
    convA_kernel<<<(S_LEN * D_MODEL / 4) / 256, 256>>>(X);
    convB_kernel<<<dim3(32, 32, 4), dim3(32, 8)>>>(Wq, Wk, Wv, Wo);
    gemm_mma<true><<<dim3(24, 16), 256, gemm_smem>>>(nullptr);
    attn_kernel<<<dim3(S_LEN / 64, N_HEADS), 256, attn_smem>>>();
    convCtx_kernel<<<(S_LEN * D_MODEL / 4) / 256, 256>>>();
    gemm_mma<false><<<dim3(8, 16), 256, gemm_smem>>>(out);
}

// round 5
// speedup vs baseline: 6.7343x; 2.1372x over previous
#include <cuda_runtime.h>
#include <cuda_bf16.h>
#include <cuda_fp16.h>
#include <math.h>
#include <cstdint>

#define S_LEN 2048
#define D_MODEL 1024
#define N_HEADS 16
#define D_KV 64
#define HSZ (S_LEN * D_KV)   // per-head plane

// ---------------- scratch (__device__ globals; no allocs) -------------------
__device__ float g_bias[N_HEADS * 4096];                        // [h][delta+2047]
__device__ __align__(16) __nv_bfloat16 g_Ah[S_LEN * D_MODEL];   // A hi (X, then ctx)
__device__ __align__(16) __nv_bfloat16 g_Al[S_LEN * D_MODEL];   // A lo
__device__ __align__(16) __nv_bfloat16 g_Bh[4096 * D_MODEL];    // W^T hi (0..3071 qkv, 3072.. Wo)
__device__ __align__(16) __nv_bfloat16 g_Bl[4096 * D_MODEL];    // W^T lo
__device__ __align__(16) __nv_bfloat16 g_Qh[N_HEADS * HSZ];     // [h][s][d]
__device__ __align__(16) __nv_bfloat16 g_Ql[N_HEADS * HSZ];
__device__ __align__(16) __nv_bfloat16 g_Kh[N_HEADS * HSZ];
__device__ __align__(16) __nv_bfloat16 g_Kl[N_HEADS * HSZ];
__device__ __align__(16) __half        g_Vh[N_HEADS * HSZ];
__device__ __align__(16) __half        g_Vl[N_HEADS * HSZ];

__device__ __forceinline__ uint32_t smem_u32(const void* p) {
    uint32_t a;
    asm("{ .reg .u64 t; cvta.to.shared.u64 t, %1; cvt.u32.u64 %0, t; }" : "=r"(a) : "l"(p));
    return a;
}

// ---------------- mma / ldmatrix / cp.async primitives ----------------------
__device__ __forceinline__ void ldm_x4(uint32_t* r, uint32_t addr) {
    asm volatile("ldmatrix.sync.aligned.m8n8.x4.shared.b16 {%0,%1,%2,%3}, [%4];"
                 : "=r"(r[0]), "=r"(r[1]), "=r"(r[2]), "=r"(r[3]) : "r"(addr));
}
__device__ __forceinline__ void ldm_x4t(uint32_t* r, uint32_t addr) {
    asm volatile("ldmatrix.sync.aligned.m8n8.x4.trans.shared.b16 {%0,%1,%2,%3}, [%4];"
                 : "=r"(r[0]), "=r"(r[1]), "=r"(r[2]), "=r"(r[3]) : "r"(addr));
}
__device__ __forceinline__ void mma_bf(float* d, const uint32_t* a, const uint32_t* b) {
    asm volatile("mma.sync.aligned.m16n8k16.row.col.f32.bf16.bf16.f32 "
                 "{%0,%1,%2,%3}, {%4,%5,%6,%7}, {%8,%9}, {%0,%1,%2,%3};"
                 : "+f"(d[0]), "+f"(d[1]), "+f"(d[2]), "+f"(d[3])
                 : "r"(a[0]), "r"(a[1]), "r"(a[2]), "r"(a[3]), "r"(b[0]), "r"(b[1]));
}
__device__ __forceinline__ void mma_hf(float* d, const uint32_t* a, const uint32_t* b) {
    asm volatile("mma.sync.aligned.m16n8k16.row.col.f32.f16.f16.f32 "
                 "{%0,%1,%2,%3}, {%4,%5,%6,%7}, {%8,%9}, {%0,%1,%2,%3};"
                 : "+f"(d[0]), "+f"(d[1]), "+f"(d[2]), "+f"(d[3])
                 : "r"(a[0]), "r"(a[1]), "r"(a[2]), "r"(a[3]), "r"(b[0]), "r"(b[1]));
}
__device__ __forceinline__ void cp16(uint32_t saddr, const void* gaddr) {
    asm volatile("cp.async.cg.shared.global [%0], [%1], 16;" :: "r"(saddr), "l"(gaddr));
}
#define CP_COMMIT() asm volatile("cp.async.commit_group;" ::: "memory")
#define CP_WAIT(n)  asm volatile("cp.async.wait_group %0;" :: "n"(n) : "memory")

__device__ __forceinline__ uint32_t pack_f16(float lo, float hi) {
    uint32_t r;
    asm("cvt.rn.f16x2.f32 %0, %1, %2;" : "=r"(r) : "f"(hi), "f"(lo));
    return r;
}

// ---------------------------------------------------------------------------
// Bias LUT
// ---------------------------------------------------------------------------
__global__ void bias_kernel(const float* __restrict__ rel_bias) {
    int idx = blockIdx.x * blockDim.x + threadIdx.x;
    if (idx >= N_HEADS * 4095) return;
    int h = idx / 4095;
    int di = idx % 4095;
    int delta = di - 2047;
    int bucket = (delta > 0) ? 16 : 0;
    int rp = abs(delta);
    if (rp < 8) {
        bucket += rp;
    } else {
        float lr = logf((float)rp * 0.125f) / 2.7725887f;
        int large = 8 + (int)(lr * 8.0f);
        bucket += (large < 15) ? large : 15;
    }
    g_bias[h * 4096 + di] = rel_bias[bucket * N_HEADS + h];
}

// ---------------------------------------------------------------------------
// fp32 -> bf16 hi/lo split converters
// ---------------------------------------------------------------------------
__global__ void convA_kernel(const float* __restrict__ X) {
    int i = (blockIdx.x * blockDim.x + threadIdx.x) * 4;
    float4 v = *(const float4*)(X + i);
    float x[4] = {v.x, v.y, v.z, v.w};
#pragma unroll
    for (int u = 0; u < 4; u++) {
        __nv_bfloat16 h = __float2bfloat16_rn(x[u]);
        g_Ah[i + u] = h;
        g_Al[i + u] = __float2bfloat16_rn(x[u] - __bfloat162float(h));
    }
}

__global__ void convB_kernel(const float* __restrict__ Wq, const float* __restrict__ Wk,
                             const float* __restrict__ Wv, const float* __restrict__ Wo) {
    const float* W = (blockIdx.z == 0) ? Wq : (blockIdx.z == 1) ? Wk
                   : (blockIdx.z == 2) ? Wv : Wo;
    __shared__ float sm[32][33];
    int n0 = blockIdx.x * 32, k0 = blockIdx.y * 32;
    int tx = threadIdx.x, ty = threadIdx.y;   // 32 x 8
#pragma unroll
    for (int j = 0; j < 4; j++)
        sm[ty + j * 8][tx] = W[(size_t)(k0 + ty + j * 8) * D_MODEL + n0 + tx];
    __syncthreads();
#pragma unroll
    for (int j = 0; j < 4; j++) {
        int n = n0 + ty + j * 8, k = k0 + tx;
        float v = sm[tx][ty + j * 8];
        __nv_bfloat16 h = __float2bfloat16_rn(v);
        size_t o = (size_t)(blockIdx.z * 1024 + n) * D_MODEL + k;
        g_Bh[o] = h;
        g_Bl[o] = __float2bfloat16_rn(v - __bfloat162float(h));
    }
}

// ---------------------------------------------------------------------------
// mma.sync bf16 GEMM (3-term hi/lo split), 128x128 tile, BK=64, double buffer.
// QKV=true: epilogue splits into Q/K bf16 hi/lo + V fp16 hi/lo head-major.
// ---------------------------------------------------------------------------
#define PITCH 72
#define TILE_E (128 * PITCH)
#define STAGE_E (4 * TILE_E)

template <bool QKV>
__global__ __launch_bounds__(256) void gemm_mma(float* __restrict__ Cout) {
    extern __shared__ __align__(16) __nv_bfloat16 sm[];
    const int t = threadIdx.x;
    const int warp = t >> 5, lane = t & 31;
    const int m0 = blockIdx.y * 128, n0 = blockIdx.x * 128;
    const int wm0 = (warp >> 1) * 32;
    const int wn0 = (warp & 1) * 64;

    const __nv_bfloat16* Bh = g_Bh + (QKV ? 0 : (size_t)3072 * D_MODEL);
    const __nv_bfloat16* Bl = g_Bl + (QKV ? 0 : (size_t)3072 * D_MODEL);

    const uint32_t sbase = smem_u32(sm);

    const int lrow[4] = { (t + 0) >> 3, (t + 256) >> 3, (t + 512) >> 3, (t + 768) >> 3 };
    const int lcol = (t & 7) * 8;

    auto issue_stage = [&](int stage, int kb) {
        uint32_t so = sbase + (uint32_t)stage * STAGE_E * 2;
#pragma unroll
        for (int p = 0; p < 4; p++) {
            int row = lrow[p];
            uint32_t sofs = ((uint32_t)row * PITCH + lcol) * 2;
            size_t ga = (size_t)(m0 + row) * D_MODEL + kb * 64 + lcol;
            size_t gb = (size_t)(n0 + row) * D_MODEL + kb * 64 + lcol;
            cp16(so + sofs,              g_Ah + ga);
            cp16(so + TILE_E * 2 + sofs, g_Al + ga);
            cp16(so + TILE_E * 4 + sofs, Bh + gb);
            cp16(so + TILE_E * 6 + sofs, Bl + gb);
        }
        CP_COMMIT();
    };

    float d[2][8][4];
#pragma unroll
    for (int i = 0; i < 2; i++)
#pragma unroll
        for (int j = 0; j < 8; j++)
#pragma unroll
            for (int u = 0; u < 4; u++) d[i][j][u] = 0.f;

    const int arow = wm0 + (lane & 15);
    const int acolq = (lane >> 4) * 8;
    const int brow2 = wn0 + (lane >> 4) * 8 + (lane & 7);
    const int bcol2 = ((lane >> 3) & 1) * 8;

    issue_stage(0, 0);

    for (int kb = 0; kb < 16; kb++) {
        if (kb + 1 < 16) {
            issue_stage((kb + 1) & 1, kb + 1);
            CP_WAIT(1);
        } else {
            CP_WAIT(0);
        }
        __syncthreads();

        uint32_t so = sbase + (uint32_t)(kb & 1) * STAGE_E * 2;
#pragma unroll
        for (int ks = 0; ks < 4; ks++) {
            uint32_t ah[2][4], al[2][4];
#pragma unroll
            for (int i = 0; i < 2; i++) {
                uint32_t aofs = ((uint32_t)(arow + i * 16) * PITCH + ks * 16 + acolq) * 2;
                ldm_x4(ah[i], so + aofs);
                ldm_x4(al[i], so + TILE_E * 2 + aofs);
            }
#pragma unroll
            for (int jp = 0; jp < 4; jp++) {
                uint32_t bofs = ((uint32_t)(brow2 + jp * 16) * PITCH + ks * 16 + bcol2) * 2;
                uint32_t bh4[4], bl4[4];
                ldm_x4(bh4, so + TILE_E * 4 + bofs);
                ldm_x4(bl4, so + TILE_E * 6 + bofs);
#pragma unroll
                for (int i = 0; i < 2; i++) {
                    mma_bf(d[i][2 * jp],     ah[i], bh4 + 0);
                    mma_bf(d[i][2 * jp],     ah[i], bl4 + 0);
                    mma_bf(d[i][2 * jp],     al[i], bh4 + 0);
                    mma_bf(d[i][2 * jp + 1], ah[i], bh4 + 2);
                    mma_bf(d[i][2 * jp + 1], ah[i], bl4 + 2);
                    mma_bf(d[i][2 * jp + 1], al[i], bh4 + 2);
                }
            }
        }
        __syncthreads();
    }

    // epilogue
#pragma unroll
    for (int i = 0; i < 2; i++) {
        int r = m0 + wm0 + i * 16 + (lane >> 2);
#pragma unroll
        for (int j = 0; j < 8; j++) {
            int n = n0 + wn0 + j * 8 + (lane & 3) * 2;
            if (QKV) {
                int z = n >> 10, hd = (n >> 6) & 15, dd = n & 63;
                size_t o0 = (size_t)hd * HSZ + (size_t)r * D_KV + dd;
                size_t o1 = o0 + 8 * D_KV;
                float2 v0 = make_float2(d[i][j][0], d[i][j][1]);
                float2 v1 = make_float2(d[i][j][2], d[i][j][3]);
                if (z < 2) {
                    __nv_bfloat16* Dh = (z == 0) ? g_Qh : g_Kh;
                    __nv_bfloat16* Dl = (z == 0) ? g_Ql : g_Kl;
                    __nv_bfloat162 h0, l0, h1, l1;
                    h0.x = __float2bfloat16_rn(v0.x); h0.y = __float2bfloat16_rn(v0.y);
                    l0.x = __float2bfloat16_rn(v0.x - __bfloat162float(h0.x));
                    l0.y = __float2bfloat16_rn(v0.y - __bfloat162float(h0.y));
                    h1.x = __float2bfloat16_rn(v1.x); h1.y = __float2bfloat16_rn(v1.y);
                    l1.x = __float2bfloat16_rn(v1.x - __bfloat162float(h1.x));
                    l1.y = __float2bfloat16_rn(v1.y - __bfloat162float(h1.y));
                    *(__nv_bfloat162*)(Dh + o0) = h0;
                    *(__nv_bfloat162*)(Dl + o0) = l0;
                    *(__nv_bfloat162*)(Dh + o1) = h1;
                    *(__nv_bfloat162*)(Dl + o1) = l1;
                } else {
                    __half2 h0, l0, h1, l1;
                    h0.x = __float2half_rn(v0.x); h0.y = __float2half_rn(v0.y);
                    l0.x = __float2half_rn(v0.x - __half2float(h0.x));
                    l0.y = __float2half_rn(v0.y - __half2float(h0.y));
                    h1.x = __float2half_rn(v1.x); h1.y = __float2half_rn(v1.y);
                    l1.x = __float2half_rn(v1.x - __half2float(h1.x));
                    l1.y = __float2half_rn(v1.y - __half2float(h1.y));
                    *(__half2*)(g_Vh + o0) = h0;
                    *(__half2*)(g_Vl + o0) = l0;
                    *(__half2*)(g_Vh + o1) = h1;
                    *(__half2*)(g_Vl + o1) = l1;
                }
            } else {
                *(float2*)(Cout + (size_t)r * D_MODEL + n) = make_float2(d[i][j][0], d[i][j][1]);
                *(float2*)(Cout + (size_t)(r + 8) * D_MODEL + n) = make_float2(d[i][j][2], d[i][j][3]);
            }
        }
    }
}

// ---------------------------------------------------------------------------
// Tensor-core flash attention.
// CTA = (head, 128 q rows), 8 warps x m16. 64-key tiles, cp.async double buf.
// QK^T: bf16 3-term split. P: fp16 from fragments. PV: fp16, V hi/lo 2-term.
// Epilogue writes ctx split (bf16 hi/lo) straight into g_Ah/g_Al.
// ---------------------------------------------------------------------------
#define AP 72
#define QH_OFF 0
#define QL_OFF (128 * AP * 2)            // 18432
#define ST_OFF (2 * 128 * AP * 2)        // 36864
#define ARR_B  (64 * AP * 2)             // 9216 bytes per staged array
#define ST_B   (4 * ARR_B)               // 36864 per stage

__global__ __launch_bounds__(256) void attn_mma() {
    extern __shared__ __align__(16) char smem[];
    const uint32_t sb = smem_u32(smem);
    const int t = threadIdx.x, w = t >> 5, lane = t & 31;
    const int h = blockIdx.y, q0 = blockIdx.x * 128;

    const __nv_bfloat16* Qh = g_Qh + (size_t)h * HSZ;
    const __nv_bfloat16* Ql = g_Ql + (size_t)h * HSZ;
    const __nv_bfloat16* Kh = g_Kh + (size_t)h * HSZ;
    const __nv_bfloat16* Kl = g_Kl + (size_t)h * HSZ;
    const __half* Vh = g_Vh + (size_t)h * HSZ;
    const __half* Vl = g_Vl + (size_t)h * HSZ;

    // stage Q (once)
    {
        int row = t >> 3, colc = (t & 7) * 8;
#pragma unroll
        for (int jj = 0; jj < 4; jj++) {
            int r = row + 32 * jj;
            uint32_t so = (uint32_t)(r * AP + colc) * 2;
            cp16(sb + QH_OFF + so, Qh + (size_t)(q0 + r) * D_KV + colc);
            cp16(sb + QL_OFF + so, Ql + (size_t)(q0 + r) * D_KV + colc);
        }
        CP_COMMIT();
    }
    auto issue_kv = [&](int slot, int i) {
        int k0 = i * 64;
        int row = t >> 3, colc = (t & 7) * 8;
        uint32_t base = sb + ST_OFF + slot * ST_B;
#pragma unroll
        for (int jj = 0; jj < 2; jj++) {
            int r = row + 32 * jj;
            uint32_t so = (uint32_t)(r * AP + colc) * 2;
            size_t g = (size_t)(k0 + r) * D_KV + colc;
            cp16(base + 0 * ARR_B + so, Kh + g);
            cp16(base + 1 * ARR_B + so, Kl + g);
            cp16(base + 2 * ARR_B + so, Vh + g);
            cp16(base + 3 * ARR_B + so, Vl + g);
        }
        CP_COMMIT();
    };
    issue_kv(0, 0);
    issue_kv(1, 1);
    CP_WAIT(2);          // Q group done
    __syncthreads();

    // Q fragments (held in regs)
    uint32_t qh[4][4], ql[4][4];
    {
        int arow = w * 16 + (lane & 15);
        int acol = (lane >> 4) * 8;
#pragma unroll
        for (int ks = 0; ks < 4; ks++) {
            uint32_t ao = (uint32_t)(arow * AP + ks * 16 + acol) * 2;
            ldm_x4(qh[ks], sb + QH_OFF + ao);
            ldm_x4(ql[ks], sb + QL_OFF + ao);
        }
    }

    float o[8][4];
#pragma unroll
    for (int j = 0; j < 8; j++)
#pragma unroll
        for (int u = 0; u < 4; u++) o[j][u] = 0.f;
    float m_r = -1e30f, m_r8 = -1e30f, l_r = 0.f, l_r8 = 0.f;

    const int cq = (lane & 3) * 2;
    const int q_r = q0 + w * 16 + (lane >> 2);
    const float* bh = g_bias + h * 4096 + 2047 - q_r;

    const int k_r = (lane >> 4) * 8 + (lane & 7);
    const int k_c = ((lane >> 3) & 1) * 8;
    const int v_r = (lane & 7) + ((lane >> 3) & 1) * 8;
    const int v_c = (lane >> 4) * 8;

    for (int i = 0; i < 32; i++) {
        CP_WAIT(1);
        __syncthreads();
        uint32_t stb = sb + ST_OFF + (i & 1) * ST_B;
        const int k0 = i * 64;

        // S = Q K^T (3-term)
        float s[8][4];
#pragma unroll
        for (int j = 0; j < 8; j++)
#pragma unroll
            for (int u = 0; u < 4; u++) s[j][u] = 0.f;
#pragma unroll
        for (int ks = 0; ks < 4; ks++) {
#pragma unroll
            for (int jp = 0; jp < 4; jp++) {
                uint32_t ko = stb + (uint32_t)((jp * 16 + k_r) * AP + ks * 16 + k_c) * 2;
                uint32_t kh4[4], kl4[4];
                ldm_x4(kh4, ko);
                ldm_x4(kl4, ko + ARR_B);
                mma_bf(s[2 * jp],     qh[ks], kh4 + 0);
                mma_bf(s[2 * jp],     qh[ks], kl4 + 0);
                mma_bf(s[2 * jp],     ql[ks], kh4 + 0);
                mma_bf(s[2 * jp + 1], qh[ks], kh4 + 2);
                mma_bf(s[2 * jp + 1], qh[ks], kl4 + 2);
                mma_bf(s[2 * jp + 1], ql[ks], kh4 + 2);
            }
        }

        // bias + row max
        float rmax = -1e30f, rmax8 = -1e30f;
#pragma unroll
        for (int j = 0; j < 8; j++) {
            const float* bp = bh + k0 + j * 8 + cq;
            s[j][0] += __ldg(bp);
            s[j][1] += __ldg(bp + 1);
            s[j][2] += __ldg(bp - 8);
            s[j][3] += __ldg(bp - 7);
            rmax  = fmaxf(rmax,  fmaxf(s[j][0], s[j][1]));
            rmax8 = fmaxf(rmax8, fmaxf(s[j][2], s[j][3]));
        }
#pragma unroll
        for (int off = 1; off <= 2; off <<= 1) {
            rmax  = fmaxf(rmax,  __shfl_xor_sync(0xffffffffu, rmax,  off));
            rmax8 = fmaxf(rmax8, __shfl_xor_sync(0xffffffffu, rmax8, off));
        }
        float mn  = fmaxf(m_r,  rmax);
        float mn8 = fmaxf(m_r8, rmax8);
        float cr  = __expf(m_r - mn);
        float cr8 = __expf(m_r8 - mn8);
        m_r = mn; m_r8 = mn8;
        float sum = 0.f, sum8 = 0.f;
#pragma unroll
        for (int j = 0; j < 8; j++) {
            s[j][0] = __expf(s[j][0] - mn);
            s[j][1] = __expf(s[j][1] - mn);
            s[j][2] = __expf(s[j][2] - mn8);
            s[j][3] = __expf(s[j][3] - mn8);
            sum  += s[j][0] + s[j][1];
            sum8 += s[j][2] + s[j][3];
        }
#pragma unroll
        for (int off = 1; off <= 2; off <<= 1) {
            sum  += __shfl_xor_sync(0xffffffffu, sum,  off);
            sum8 += __shfl_xor_sync(0xffffffffu, sum8, off);
        }
        l_r  = l_r  * cr  + sum;
        l_r8 = l_r8 * cr8 + sum8;
#pragma unroll
        for (int j = 0; j < 8; j++) {
            o[j][0] *= cr;  o[j][1] *= cr;
            o[j][2] *= cr8; o[j][3] *= cr8;
        }

        // P fragments (fp16) straight from score regs
        uint32_t pa[4][4];
#pragma unroll
        for (int ks = 0; ks < 4; ks++) {
            pa[ks][0] = pack_f16(s[2 * ks][0], s[2 * ks][1]);
            pa[ks][1] = pack_f16(s[2 * ks][2], s[2 * ks][3]);
            pa[ks][2] = pack_f16(s[2 * ks + 1][0], s[2 * ks + 1][1]);
            pa[ks][3] = pack_f16(s[2 * ks + 1][2], s[2 * ks + 1][3]);
        }

        // O += P V (V hi/lo 2-term)
#pragma unroll
        for (int ks = 0; ks < 4; ks++) {
#pragma unroll
            for (int jp = 0; jp < 4; jp++) {
                uint32_t vo = stb + 2 * ARR_B +
                              (uint32_t)((ks * 16 + v_r) * AP + jp * 16 + v_c) * 2;
                uint32_t vh4[4], vl4[4];
                ldm_x4t(vh4, vo);
                ldm_x4t(vl4, vo + ARR_B);
                mma_hf(o[2 * jp],     pa[ks], vh4 + 0);
                mma_hf(o[2 * jp],     pa[ks], vl4 + 0);
                mma_hf(o[2 * jp + 1], pa[ks], vh4 + 2);
                mma_hf(o[2 * jp + 1], pa[ks], vl4 + 2);
            }
        }

        __syncthreads();
        if (i + 2 < 32) issue_kv(i & 1, i + 2);
    }

    // epilogue: ctx split bf16 hi/lo directly into out-gemm A buffers
    float ir = 1.f / l_r, ir8 = 1.f / l_r8;
#pragma unroll
    for (int j = 0; j < 8; j++) {
        int col = h * 64 + j * 8 + cq;
        size_t o0 = (size_t)q_r * D_MODEL + col;
        size_t o1 = o0 + 8 * D_MODEL;
        float2 v0 = make_float2(o[j][0] * ir, o[j][1] * ir);
        float2 v1 = make_float2(o[j][2] * ir8, o[j][3] * ir8);
        __nv_bfloat162 h0, l0, h1, l1;
        h0.x = __float2bfloat16_rn(v0.x); h0.y = __float2bfloat16_rn(v0.y);
        l0.x = __float2bfloat16_rn(v0.x - __bfloat162float(h0.x));
        l0.y = __float2bfloat16_rn(v0.y - __bfloat162float(h0.y));
        h1.x = __float2bfloat16_rn(v1.x); h1.y = __float2bfloat16_rn(v1.y);
        l1.x = __float2bfloat16_rn(v1.x - __bfloat162float(h1.x));
        l1.y = __float2bfloat16_rn(v1.y - __bfloat162float(h1.y));
        *(__nv_bfloat162*)(g_Ah + o0) = h0;
        *(__nv_bfloat162*)(g_Al + o0) = l0;
        *(__nv_bfloat162*)(g_Ah + o1) = h1;
        *(__nv_bfloat162*)(g_Al + o1) = l1;
    }
}

// ---------------------------------------------------------------------------
extern "C" void kernel_launch(void* const* d_in, const int* in_sizes, int n_in,
                              void* d_out, int out_size) {
    const float* X   = (const float*)d_in[0];
    const float* Wq  = (const float*)d_in[1];
    const float* Wk  = (const float*)d_in[2];
    const float* Wv  = (const float*)d_in[3];
    const float* Wo  = (const float*)d_in[4];
    const float* rel = (const float*)d_in[5];
    float* out = (float*)d_out;

    const int gemm_smem = 2 * STAGE_E * 2;                 // 147456
    const int attn_smem = ST_OFF + 2 * ST_B;               // 110592
    cudaFuncSetAttribute(gemm_mma<true>,  cudaFuncAttributeMaxDynamicSharedMemorySize, gemm_smem);
    cudaFuncSetAttribute(gemm_mma<false>, cudaFuncAttributeMaxDynamicSharedMemorySize, gemm_smem);
    cudaFuncSetAttribute(attn_mma,        cudaFuncAttributeMaxDynamicSharedMemorySize, attn_smem);

    bias_kernel<<<(N_HEADS * 4095 + 255) / 256, 256>>>(rel);
    convA_kernel<<<(S_LEN * D_MODEL / 4) / 256, 256>>>(X);
    convB_kernel<<<dim3(32, 32, 4), dim3(32, 8)>>>(Wq, Wk, Wv, Wo);
    gemm_mma<true><<<dim3(24, 16), 256, gemm_smem>>>(nullptr);
    attn_mma<<<dim3(16, 16), 256, attn_smem>>>();
    gemm_mma<false><<<dim3(8, 16), 256, gemm_smem>>>(out);
}

// round 6
// speedup vs baseline: 6.8589x; 1.0185x over previous
#include <cuda_runtime.h>
#include <cuda_bf16.h>
#include <cuda_fp16.h>
#include <math.h>
#include <cstdint>

#define S_LEN 2048
#define D_MODEL 1024
#define N_HEADS 16
#define D_KV 64
#define HSZ (S_LEN * D_KV)   // per-head plane

// ---------------- scratch (__device__ globals; no allocs) -------------------
__device__ float g_bias[N_HEADS * 4096];                        // [h][delta+2047]
__device__ __align__(16) __nv_bfloat16 g_Ah[S_LEN * D_MODEL];   // A hi (X, then ctx)
__device__ __align__(16) __nv_bfloat16 g_Al[S_LEN * D_MODEL];   // A lo
__device__ __align__(16) __nv_bfloat16 g_Bh[4096 * D_MODEL];    // W^T hi (0..3071 qkv, 3072.. Wo)
__device__ __align__(16) __nv_bfloat16 g_Bl[4096 * D_MODEL];    // W^T lo
__device__ __align__(16) __nv_bfloat16 g_Qh[N_HEADS * HSZ];     // [h][s][d]
__device__ __align__(16) __nv_bfloat16 g_Ql[N_HEADS * HSZ];
__device__ __align__(16) __nv_bfloat16 g_Kh[N_HEADS * HSZ];
__device__ __align__(16) __nv_bfloat16 g_Kl[N_HEADS * HSZ];
__device__ __align__(16) __half        g_Vh[N_HEADS * HSZ];
__device__ __align__(16) __half        g_Vl[N_HEADS * HSZ];

__device__ __forceinline__ uint32_t smem_u32(const void* p) {
    uint32_t a;
    asm("{ .reg .u64 t; cvta.to.shared.u64 t, %1; cvt.u32.u64 %0, t; }" : "=r"(a) : "l"(p));
    return a;
}

// ---------------- mma / ldmatrix / cp.async primitives ----------------------
__device__ __forceinline__ void ldm_x4(uint32_t* r, uint32_t addr) {
    asm volatile("ldmatrix.sync.aligned.m8n8.x4.shared.b16 {%0,%1,%2,%3}, [%4];"
                 : "=r"(r[0]), "=r"(r[1]), "=r"(r[2]), "=r"(r[3]) : "r"(addr));
}
__device__ __forceinline__ void ldm_x4t(uint32_t* r, uint32_t addr) {
    asm volatile("ldmatrix.sync.aligned.m8n8.x4.trans.shared.b16 {%0,%1,%2,%3}, [%4];"
                 : "=r"(r[0]), "=r"(r[1]), "=r"(r[2]), "=r"(r[3]) : "r"(addr));
}
__device__ __forceinline__ void mma_bf(float* d, const uint32_t* a, const uint32_t* b) {
    asm volatile("mma.sync.aligned.m16n8k16.row.col.f32.bf16.bf16.f32 "
                 "{%0,%1,%2,%3}, {%4,%5,%6,%7}, {%8,%9}, {%0,%1,%2,%3};"
                 : "+f"(d[0]), "+f"(d[1]), "+f"(d[2]), "+f"(d[3])
                 : "r"(a[0]), "r"(a[1]), "r"(a[2]), "r"(a[3]), "r"(b[0]), "r"(b[1]));
}
__device__ __forceinline__ void mma_hf(float* d, const uint32_t* a, const uint32_t* b) {
    asm volatile("mma.sync.aligned.m16n8k16.row.col.f32.f16.f16.f32 "
                 "{%0,%1,%2,%3}, {%4,%5,%6,%7}, {%8,%9}, {%0,%1,%2,%3};"
                 : "+f"(d[0]), "+f"(d[1]), "+f"(d[2]), "+f"(d[3])
                 : "r"(a[0]), "r"(a[1]), "r"(a[2]), "r"(a[3]), "r"(b[0]), "r"(b[1]));
}
__device__ __forceinline__ void cp16(uint32_t saddr, const void* gaddr) {
    asm volatile("cp.async.cg.shared.global [%0], [%1], 16;" :: "r"(saddr), "l"(gaddr));
}
#define CP_COMMIT() asm volatile("cp.async.commit_group;" ::: "memory")
#define CP_WAIT(n)  asm volatile("cp.async.wait_group %0;" :: "n"(n) : "memory")

__device__ __forceinline__ uint32_t pack_f16(float lo, float hi) {
    uint32_t r;
    asm("cvt.rn.f16x2.f32 %0, %1, %2;" : "=r"(r) : "f"(hi), "f"(lo));
    return r;
}

// ---------------------------------------------------------------------------
// Bias LUT
// ---------------------------------------------------------------------------
__global__ void bias_kernel(const float* __restrict__ rel_bias) {
    int idx = blockIdx.x * blockDim.x + threadIdx.x;
    if (idx >= N_HEADS * 4095) return;
    int h = idx / 4095;
    int di = idx % 4095;
    int delta = di - 2047;
    int bucket = (delta > 0) ? 16 : 0;
    int rp = abs(delta);
    if (rp < 8) {
        bucket += rp;
    } else {
        float lr = logf((float)rp * 0.125f) / 2.7725887f;
        int large = 8 + (int)(lr * 8.0f);
        bucket += (large < 15) ? large : 15;
    }
    g_bias[h * 4096 + di] = rel_bias[bucket * N_HEADS + h];
}

// ---------------------------------------------------------------------------
// fp32 -> bf16 hi/lo split converters
// ---------------------------------------------------------------------------
__global__ void convA_kernel(const float* __restrict__ X) {
    int i = (blockIdx.x * blockDim.x + threadIdx.x) * 4;
    float4 v = *(const float4*)(X + i);
    float x[4] = {v.x, v.y, v.z, v.w};
#pragma unroll
    for (int u = 0; u < 4; u++) {
        __nv_bfloat16 h = __float2bfloat16_rn(x[u]);
        g_Ah[i + u] = h;
        g_Al[i + u] = __float2bfloat16_rn(x[u] - __bfloat162float(h));
    }
}

__global__ void convB_kernel(const float* __restrict__ Wq, const float* __restrict__ Wk,
                             const float* __restrict__ Wv, const float* __restrict__ Wo) {
    const float* W = (blockIdx.z == 0) ? Wq : (blockIdx.z == 1) ? Wk
                   : (blockIdx.z == 2) ? Wv : Wo;
    __shared__ float sm[32][33];
    int n0 = blockIdx.x * 32, k0 = blockIdx.y * 32;
    int tx = threadIdx.x, ty = threadIdx.y;   // 32 x 8
#pragma unroll
    for (int j = 0; j < 4; j++)
        sm[ty + j * 8][tx] = W[(size_t)(k0 + ty + j * 8) * D_MODEL + n0 + tx];
    __syncthreads();
#pragma unroll
    for (int j = 0; j < 4; j++) {
        int n = n0 + ty + j * 8, k = k0 + tx;
        float v = sm[tx][ty + j * 8];
        __nv_bfloat16 h = __float2bfloat16_rn(v);
        size_t o = (size_t)(blockIdx.z * 1024 + n) * D_MODEL + k;
        g_Bh[o] = h;
        g_Bl[o] = __float2bfloat16_rn(v - __bfloat162float(h));
    }
}

// ---------------------------------------------------------------------------
// mma.sync bf16 GEMM (3-term hi/lo split), 128x128 tile, BK=32, double buffer.
// 2 CTAs/SM (82KB smem, regs capped at 128).
// ---------------------------------------------------------------------------
#define PITCH 40                        // 32 + 8 pad (80B rows: conflict-free ldmatrix)
#define TILE_E (128 * PITCH)            // 5120 bf16
#define STAGE_E (4 * TILE_E)            // Ah,Al,Bh,Bl -> 40960 B/stage

template <bool QKV>
__global__ __launch_bounds__(256, 2) void gemm_mma(float* __restrict__ Cout) {
    extern __shared__ __align__(16) __nv_bfloat16 sm[];
    const int t = threadIdx.x;
    const int warp = t >> 5, lane = t & 31;
    const int m0 = blockIdx.y * 128, n0 = blockIdx.x * 128;
    const int wm0 = (warp >> 1) * 32;
    const int wn0 = (warp & 1) * 64;

    const __nv_bfloat16* Bh = g_Bh + (QKV ? 0 : (size_t)3072 * D_MODEL);
    const __nv_bfloat16* Bl = g_Bl + (QKV ? 0 : (size_t)3072 * D_MODEL);

    const uint32_t sbase = smem_u32(sm);

    // loader: per array 128 rows x 4 chunks(16B) = 512 chunks; 2 per thread
    const int lrow[2] = { t >> 2, (t + 256) >> 2 };
    const int lcol = (t & 3) * 8;

    auto issue_stage = [&](int stage, int kb) {
        uint32_t so = sbase + (uint32_t)stage * STAGE_E * 2;
#pragma unroll
        for (int p = 0; p < 2; p++) {
            int row = lrow[p];
            uint32_t sofs = ((uint32_t)row * PITCH + lcol) * 2;
            size_t ga = (size_t)(m0 + row) * D_MODEL + kb * 32 + lcol;
            size_t gb = (size_t)(n0 + row) * D_MODEL + kb * 32 + lcol;
            cp16(so + sofs,              g_Ah + ga);
            cp16(so + TILE_E * 2 + sofs, g_Al + ga);
            cp16(so + TILE_E * 4 + sofs, Bh + gb);
            cp16(so + TILE_E * 6 + sofs, Bl + gb);
        }
        CP_COMMIT();
    };

    float d[2][8][4];
#pragma unroll
    for (int i = 0; i < 2; i++)
#pragma unroll
        for (int j = 0; j < 8; j++)
#pragma unroll
            for (int u = 0; u < 4; u++) d[i][j][u] = 0.f;

    const int arow = wm0 + (lane & 15);
    const int acolq = (lane >> 4) * 8;
    const int brow2 = wn0 + (lane >> 4) * 8 + (lane & 7);
    const int bcol2 = ((lane >> 3) & 1) * 8;

    issue_stage(0, 0);

    for (int kb = 0; kb < 32; kb++) {
        if (kb + 1 < 32) {
            issue_stage((kb + 1) & 1, kb + 1);
            CP_WAIT(1);
        } else {
            CP_WAIT(0);
        }
        __syncthreads();

        uint32_t so = sbase + (uint32_t)(kb & 1) * STAGE_E * 2;
#pragma unroll
        for (int ks = 0; ks < 2; ks++) {
            uint32_t ah[2][4], al[2][4];
#pragma unroll
            for (int i = 0; i < 2; i++) {
                uint32_t aofs = ((uint32_t)(arow + i * 16) * PITCH + ks * 16 + acolq) * 2;
                ldm_x4(ah[i], so + aofs);
                ldm_x4(al[i], so + TILE_E * 2 + aofs);
            }
#pragma unroll
            for (int jp = 0; jp < 4; jp++) {
                uint32_t bofs = ((uint32_t)(brow2 + jp * 16) * PITCH + ks * 16 + bcol2) * 2;
                uint32_t bh4[4], bl4[4];
                ldm_x4(bh4, so + TILE_E * 4 + bofs);
                ldm_x4(bl4, so + TILE_E * 6 + bofs);
#pragma unroll
                for (int i = 0; i < 2; i++) {
                    mma_bf(d[i][2 * jp],     ah[i], bh4 + 0);
                    mma_bf(d[i][2 * jp],     ah[i], bl4 + 0);
                    mma_bf(d[i][2 * jp],     al[i], bh4 + 0);
                    mma_bf(d[i][2 * jp + 1], ah[i], bh4 + 2);
                    mma_bf(d[i][2 * jp + 1], ah[i], bl4 + 2);
                    mma_bf(d[i][2 * jp + 1], al[i], bh4 + 2);
                }
            }
        }
        __syncthreads();
    }

    // epilogue
#pragma unroll
    for (int i = 0; i < 2; i++) {
        int r = m0 + wm0 + i * 16 + (lane >> 2);
#pragma unroll
        for (int j = 0; j < 8; j++) {
            int n = n0 + wn0 + j * 8 + (lane & 3) * 2;
            if (QKV) {
                int z = n >> 10, hd = (n >> 6) & 15, dd = n & 63;
                size_t o0 = (size_t)hd * HSZ + (size_t)r * D_KV + dd;
                size_t o1 = o0 + 8 * D_KV;
                float2 v0 = make_float2(d[i][j][0], d[i][j][1]);
                float2 v1 = make_float2(d[i][j][2], d[i][j][3]);
                if (z < 2) {
                    __nv_bfloat16* Dh = (z == 0) ? g_Qh : g_Kh;
                    __nv_bfloat16* Dl = (z == 0) ? g_Ql : g_Kl;
                    __nv_bfloat162 h0, l0, h1, l1;
                    h0.x = __float2bfloat16_rn(v0.x); h0.y = __float2bfloat16_rn(v0.y);
                    l0.x = __float2bfloat16_rn(v0.x - __bfloat162float(h0.x));
                    l0.y = __float2bfloat16_rn(v0.y - __bfloat162float(h0.y));
                    h1.x = __float2bfloat16_rn(v1.x); h1.y = __float2bfloat16_rn(v1.y);
                    l1.x = __float2bfloat16_rn(v1.x - __bfloat162float(h1.x));
                    l1.y = __float2bfloat16_rn(v1.y - __bfloat162float(h1.y));
                    *(__nv_bfloat162*)(Dh + o0) = h0;
                    *(__nv_bfloat162*)(Dl + o0) = l0;
                    *(__nv_bfloat162*)(Dh + o1) = h1;
                    *(__nv_bfloat162*)(Dl + o1) = l1;
                } else {
                    __half2 h0, l0, h1, l1;
                    h0.x = __float2half_rn(v0.x); h0.y = __float2half_rn(v0.y);
                    l0.x = __float2half_rn(v0.x - __half2float(h0.x));
                    l0.y = __float2half_rn(v0.y - __half2float(h0.y));
                    h1.x = __float2half_rn(v1.x); h1.y = __float2half_rn(v1.y);
                    l1.x = __float2half_rn(v1.x - __half2float(h1.x));
                    l1.y = __float2half_rn(v1.y - __half2float(h1.y));
                    *(__half2*)(g_Vh + o0) = h0;
                    *(__half2*)(g_Vl + o0) = l0;
                    *(__half2*)(g_Vh + o1) = h1;
                    *(__half2*)(g_Vl + o1) = l1;
                }
            } else {
                *(float2*)(Cout + (size_t)r * D_MODEL + n) = make_float2(d[i][j][0], d[i][j][1]);
                *(float2*)(Cout + (size_t)(r + 8) * D_MODEL + n) = make_float2(d[i][j][2], d[i][j][3]);
            }
        }
    }
}

// ---------------------------------------------------------------------------
// Tensor-core flash attention (2 CTAs/SM: 110.6KB smem, regs capped 128).
// CTA = (head, 128 q rows), 8 warps x m16. 64-key tiles, cp.async double buf.
// ---------------------------------------------------------------------------
#define AP 72
#define QH_OFF 0
#define QL_OFF (128 * AP * 2)            // 18432
#define ST_OFF (2 * 128 * AP * 2)        // 36864
#define ARR_B  (64 * AP * 2)             // 9216 bytes per staged array
#define ST_B   (4 * ARR_B)               // 36864 per stage

__global__ __launch_bounds__(256, 2) void attn_mma() {
    extern __shared__ __align__(16) char smem[];
    const uint32_t sb = smem_u32(smem);
    const int t = threadIdx.x, w = t >> 5, lane = t & 31;
    const int h = blockIdx.y, q0 = blockIdx.x * 128;

    const __nv_bfloat16* Qh = g_Qh + (size_t)h * HSZ;
    const __nv_bfloat16* Ql = g_Ql + (size_t)h * HSZ;
    const __nv_bfloat16* Kh = g_Kh + (size_t)h * HSZ;
    const __nv_bfloat16* Kl = g_Kl + (size_t)h * HSZ;
    const __half* Vh = g_Vh + (size_t)h * HSZ;
    const __half* Vl = g_Vl + (size_t)h * HSZ;

    // stage Q (once)
    {
        int row = t >> 3, colc = (t & 7) * 8;
#pragma unroll
        for (int jj = 0; jj < 4; jj++) {
            int r = row + 32 * jj;
            uint32_t so = (uint32_t)(r * AP + colc) * 2;
            cp16(sb + QH_OFF + so, Qh + (size_t)(q0 + r) * D_KV + colc);
            cp16(sb + QL_OFF + so, Ql + (size_t)(q0 + r) * D_KV + colc);
        }
        CP_COMMIT();
    }
    auto issue_kv = [&](int slot, int i) {
        int k0 = i * 64;
        int row = t >> 3, colc = (t & 7) * 8;
        uint32_t base = sb + ST_OFF + slot * ST_B;
#pragma unroll
        for (int jj = 0; jj < 2; jj++) {
            int r = row + 32 * jj;
            uint32_t so = (uint32_t)(r * AP + colc) * 2;
            size_t g = (size_t)(k0 + r) * D_KV + colc;
            cp16(base + 0 * ARR_B + so, Kh + g);
            cp16(base + 1 * ARR_B + so, Kl + g);
            cp16(base + 2 * ARR_B + so, Vh + g);
            cp16(base + 3 * ARR_B + so, Vl + g);
        }
        CP_COMMIT();
    };
    issue_kv(0, 0);
    issue_kv(1, 1);
    CP_WAIT(2);          // Q group done
    __syncthreads();

    // Q fragments (held in regs)
    uint32_t qh[4][4], ql[4][4];
    {
        int arow = w * 16 + (lane & 15);
        int acol = (lane >> 4) * 8;
#pragma unroll
        for (int ks = 0; ks < 4; ks++) {
            uint32_t ao = (uint32_t)(arow * AP + ks * 16 + acol) * 2;
            ldm_x4(qh[ks], sb + QH_OFF + ao);
            ldm_x4(ql[ks], sb + QL_OFF + ao);
        }
    }

    float o[8][4];
#pragma unroll
    for (int j = 0; j < 8; j++)
#pragma unroll
        for (int u = 0; u < 4; u++) o[j][u] = 0.f;
    float m_r = -1e30f, m_r8 = -1e30f, l_r = 0.f, l_r8 = 0.f;

    const int cq = (lane & 3) * 2;
    const int q_r = q0 + w * 16 + (lane >> 2);
    const float* bh = g_bias + h * 4096 + 2047 - q_r;

    const int k_r = (lane >> 4) * 8 + (lane & 7);
    const int k_c = ((lane >> 3) & 1) * 8;
    const int v_r = (lane & 7) + ((lane >> 3) & 1) * 8;
    const int v_c = (lane >> 4) * 8;

    for (int i = 0; i < 32; i++) {
        CP_WAIT(1);
        __syncthreads();
        uint32_t stb = sb + ST_OFF + (i & 1) * ST_B;
        const int k0 = i * 64;

        // S = Q K^T (3-term)
        float s[8][4];
#pragma unroll
        for (int j = 0; j < 8; j++)
#pragma unroll
            for (int u = 0; u < 4; u++) s[j][u] = 0.f;
#pragma unroll
        for (int ks = 0; ks < 4; ks++) {
#pragma unroll
            for (int jp = 0; jp < 4; jp++) {
                uint32_t ko = stb + (uint32_t)((jp * 16 + k_r) * AP + ks * 16 + k_c) * 2;
                uint32_t kh4[4], kl4[4];
                ldm_x4(kh4, ko);
                ldm_x4(kl4, ko + ARR_B);
                mma_bf(s[2 * jp],     qh[ks], kh4 + 0);
                mma_bf(s[2 * jp],     qh[ks], kl4 + 0);
                mma_bf(s[2 * jp],     ql[ks], kh4 + 0);
                mma_bf(s[2 * jp + 1], qh[ks], kh4 + 2);
                mma_bf(s[2 * jp + 1], qh[ks], kl4 + 2);
                mma_bf(s[2 * jp + 1], ql[ks], kh4 + 2);
            }
        }

        // bias + row max
        float rmax = -1e30f, rmax8 = -1e30f;
#pragma unroll
        for (int j = 0; j < 8; j++) {
            const float* bp = bh + k0 + j * 8 + cq;
            s[j][0] += __ldg(bp);
            s[j][1] += __ldg(bp + 1);
            s[j][2] += __ldg(bp - 8);
            s[j][3] += __ldg(bp - 7);
            rmax  = fmaxf(rmax,  fmaxf(s[j][0], s[j][1]));
            rmax8 = fmaxf(rmax8, fmaxf(s[j][2], s[j][3]));
        }
#pragma unroll
        for (int off = 1; off <= 2; off <<= 1) {
            rmax  = fmaxf(rmax,  __shfl_xor_sync(0xffffffffu, rmax,  off));
            rmax8 = fmaxf(rmax8, __shfl_xor_sync(0xffffffffu, rmax8, off));
        }
        float mn  = fmaxf(m_r,  rmax);
        float mn8 = fmaxf(m_r8, rmax8);
        float cr  = __expf(m_r - mn);
        float cr8 = __expf(m_r8 - mn8);
        m_r = mn; m_r8 = mn8;
        float sum = 0.f, sum8 = 0.f;
#pragma unroll
        for (int j = 0; j < 8; j++) {
            s[j][0] = __expf(s[j][0] - mn);
            s[j][1] = __expf(s[j][1] - mn);
            s[j][2] = __expf(s[j][2] - mn8);
            s[j][3] = __expf(s[j][3] - mn8);
            sum  += s[j][0] + s[j][1];
            sum8 += s[j][2] + s[j][3];
        }
#pragma unroll
        for (int off = 1; off <= 2; off <<= 1) {
            sum  += __shfl_xor_sync(0xffffffffu, sum,  off);
            sum8 += __shfl_xor_sync(0xffffffffu, sum8, off);
        }
        l_r  = l_r  * cr  + sum;
        l_r8 = l_r8 * cr8 + sum8;
#pragma unroll
        for (int j = 0; j < 8; j++) {
            o[j][0] *= cr;  o[j][1] *= cr;
            o[j][2] *= cr8; o[j][3] *= cr8;
        }

        // P fragments (fp16) straight from score regs
        uint32_t pa[4][4];
#pragma unroll
        for (int ks = 0; ks < 4; ks++) {
            pa[ks][0] = pack_f16(s[2 * ks][0], s[2 * ks][1]);
            pa[ks][1] = pack_f16(s[2 * ks][2], s[2 * ks][3]);
            pa[ks][2] = pack_f16(s[2 * ks + 1][0], s[2 * ks + 1][1]);
            pa[ks][3] = pack_f16(s[2 * ks + 1][2], s[2 * ks + 1][3]);
        }

        // O += P V (V hi/lo 2-term)
#pragma unroll
        for (int ks = 0; ks < 4; ks++) {
#pragma unroll
            for (int jp = 0; jp < 4; jp++) {
                uint32_t vo = stb + 2 * ARR_B +
                              (uint32_t)((ks * 16 + v_r) * AP + jp * 16 + v_c) * 2;
                uint32_t vh4[4], vl4[4];
                ldm_x4t(vh4, vo);
                ldm_x4t(vl4, vo + ARR_B);
                mma_hf(o[2 * jp],     pa[ks], vh4 + 0);
                mma_hf(o[2 * jp],     pa[ks], vl4 + 0);
                mma_hf(o[2 * jp + 1], pa[ks], vh4 + 2);
                mma_hf(o[2 * jp + 1], pa[ks], vl4 + 2);
            }
        }

        __syncthreads();
        if (i + 2 < 32) issue_kv(i & 1, i + 2);
    }

    // epilogue: ctx split bf16 hi/lo directly into out-gemm A buffers
    float ir = 1.f / l_r, ir8 = 1.f / l_r8;
#pragma unroll
    for (int j = 0; j < 8; j++) {
        int col = h * 64 + j * 8 + cq;
        size_t o0 = (size_t)q_r * D_MODEL + col;
        size_t o1 = o0 + 8 * D_MODEL;
        float2 v0 = make_float2(o[j][0] * ir, o[j][1] * ir);
        float2 v1 = make_float2(o[j][2] * ir8, o[j][3] * ir8);
        __nv_bfloat162 h0, l0, h1, l1;
        h0.x = __float2bfloat16_rn(v0.x); h0.y = __float2bfloat16_rn(v0.y);
        l0.x = __float2bfloat16_rn(v0.x - __bfloat162float(h0.x));
        l0.y = __float2bfloat16_rn(v0.y - __bfloat162float(h0.y));
        h1.x = __float2bfloat16_rn(v1.x); h1.y = __float2bfloat16_rn(v1.y);
        l1.x = __float2bfloat16_rn(v1.x - __bfloat162float(h1.x));
        l1.y = __float2bfloat16_rn(v1.y - __bfloat162float(h1.y));
        *(__nv_bfloat162*)(g_Ah + o0) = h0;
        *(__nv_bfloat162*)(g_Al + o0) = l0;
        *(__nv_bfloat162*)(g_Ah + o1) = h1;
        *(__nv_bfloat162*)(g_Al + o1) = l1;
    }
}

// ---------------------------------------------------------------------------
extern "C" void kernel_launch(void* const* d_in, const int* in_sizes, int n_in,
                              void* d_out, int out_size) {
    const float* X   = (const float*)d_in[0];
    const float* Wq  = (const float*)d_in[1];
    const float* Wk  = (const float*)d_in[2];
    const float* Wv  = (const float*)d_in[3];
    const float* Wo  = (const float*)d_in[4];
    const float* rel = (const float*)d_in[5];
    float* out = (float*)d_out;

    const int gemm_smem = 2 * STAGE_E * 2;                 // 81920
    const int attn_smem = ST_OFF + 2 * ST_B;               // 110592
    cudaFuncSetAttribute(gemm_mma<true>,  cudaFuncAttributeMaxDynamicSharedMemorySize, gemm_smem);
    cudaFuncSetAttribute(gemm_mma<false>, cudaFuncAttributeMaxDynamicSharedMemorySize, gemm_smem);
    cudaFuncSetAttribute(attn_mma,        cudaFuncAttributeMaxDynamicSharedMemorySize, attn_smem);

    bias_kernel<<<(N_HEADS * 4095 + 255) / 256, 256>>>(rel);
    convA_kernel<<<(S_LEN * D_MODEL / 4) / 256, 256>>>(X);
    convB_kernel<<<dim3(32, 32, 4), dim3(32, 8)>>>(Wq, Wk, Wv, Wo);
    gemm_mma<true><<<dim3(24, 16), 256, gemm_smem>>>(nullptr);
    attn_mma<<<dim3(16, 16), 256, attn_smem>>>();
    gemm_mma<false><<<dim3(8, 16), 256, gemm_smem>>>(out);
}

// round 8
// speedup vs baseline: 9.5543x; 1.3930x over previous
#include <cuda_runtime.h>
#include <cuda_fp16.h>
#include <math.h>
#include <cstdint>

#define S_LEN 2048
#define D_MODEL 1024
#define N_HEADS 16
#define D_KV 64
#define KE 2048              // extended K (hi|lo)
#define HSZ (S_LEN * 128)    // per-head Q'/K' plane (d'=128)
#define HSZV (S_LEN * 64)    // per-head V plane

// ---------------- scratch (__device__ globals; no allocs) -------------------
__device__ float g_bias[N_HEADS * 4096];                 // [h][delta+2047]
__device__ __align__(16) __half g_A2[S_LEN * KE];        // A' rows: [hi(1024) | lo(1024)]
__device__ __align__(16) __half g_B2[4096 * KE];         // B' rows: [hi+lo | hi], W x256
__device__ __align__(16) __half g_Q2[N_HEADS * HSZ];     // [h][s][ Qh(64) | Ql(64) ]
__device__ __align__(16) __half g_K2[N_HEADS * HSZ];     // [h][s][ Kh+Kl(64) | Kh(64) ]
__device__ __align__(16) __half g_V [N_HEADS * HSZV];    // [h][s][64] single fp16

__device__ __forceinline__ uint32_t smem_u32(const void* p) {
    uint32_t a;
    asm("{ .reg .u64 t; cvta.to.shared.u64 t, %1; cvt.u32.u64 %0, t; }" : "=r"(a) : "l"(p));
    return a;
}

// ---------------- mma / ldmatrix / cp.async primitives ----------------------
__device__ __forceinline__ void ldm_x4(uint32_t* r, uint32_t addr) {
    asm volatile("ldmatrix.sync.aligned.m8n8.x4.shared.b16 {%0,%1,%2,%3}, [%4];"
                 : "=r"(r[0]), "=r"(r[1]), "=r"(r[2]), "=r"(r[3]) : "r"(addr));
}
__device__ __forceinline__ void ldm_x4t(uint32_t* r, uint32_t addr) {
    asm volatile("ldmatrix.sync.aligned.m8n8.x4.trans.shared.b16 {%0,%1,%2,%3}, [%4];"
                 : "=r"(r[0]), "=r"(r[1]), "=r"(r[2]), "=r"(r[3]) : "r"(addr));
}
__device__ __forceinline__ void mma_hf(float* d, const uint32_t* a, const uint32_t* b) {
    asm volatile("mma.sync.aligned.m16n8k16.row.col.f32.f16.f16.f32 "
                 "{%0,%1,%2,%3}, {%4,%5,%6,%7}, {%8,%9}, {%0,%1,%2,%3};"
                 : "+f"(d[0]), "+f"(d[1]), "+f"(d[2]), "+f"(d[3])
                 : "r"(a[0]), "r"(a[1]), "r"(a[2]), "r"(a[3]), "r"(b[0]), "r"(b[1]));
}
__device__ __forceinline__ void cp16(uint32_t saddr, const void* gaddr) {
    asm volatile("cp.async.cg.shared.global [%0], [%1], 16;" :: "r"(saddr), "l"(gaddr));
}
#define CP_COMMIT() asm volatile("cp.async.commit_group;" ::: "memory")
#define CP_WAIT(n)  asm volatile("cp.async.wait_group %0;" :: "n"(n) : "memory")

__device__ __forceinline__ uint32_t pack_f16(float lo, float hi) {
    uint32_t r;
    asm("cvt.rn.f16x2.f32 %0, %1, %2;" : "=r"(r) : "f"(hi), "f"(lo));
    return r;
}

// ---------------------------------------------------------------------------
// Bias LUT
// ---------------------------------------------------------------------------
__global__ void bias_kernel(const float* __restrict__ rel_bias) {
    int idx = blockIdx.x * blockDim.x + threadIdx.x;
    if (idx >= N_HEADS * 4095) return;
    int h = idx / 4095;
    int di = idx % 4095;
    int delta = di - 2047;
    int bucket = (delta > 0) ? 16 : 0;
    int rp = abs(delta);
    if (rp < 8) {
        bucket += rp;
    } else {
        float lr = logf((float)rp * 0.125f) / 2.7725887f;
        int large = 8 + (int)(lr * 8.0f);
        bucket += (large < 15) ? large : 15;
    }
    g_bias[h * 4096 + di] = rel_bias[bucket * N_HEADS + h];
}

// ---------------------------------------------------------------------------
// Converters: fp32 -> fp16 hi/lo extended-K
// ---------------------------------------------------------------------------
__global__ void convA_kernel(const float* __restrict__ X) {
    int i = (blockIdx.x * blockDim.x + threadIdx.x) * 4;   // over 2048x1024
    int row = i >> 10, col = i & 1023;
    float4 v = *(const float4*)(X + i);
    float x[4] = {v.x, v.y, v.z, v.w};
    __half hi[4], lo[4];
#pragma unroll
    for (int u = 0; u < 4; u++) {
        hi[u] = __float2half_rn(x[u]);
        lo[u] = __float2half_rn(x[u] - __half2float(hi[u]));
    }
    __half* dst = g_A2 + (size_t)row * KE + col;
    *(__half2*)(dst + 0) = __halves2half2(hi[0], hi[1]);
    *(__half2*)(dst + 2) = __halves2half2(hi[2], hi[3]);
    *(__half2*)(dst + 1024) = __halves2half2(lo[0], lo[1]);
    *(__half2*)(dst + 1026) = __halves2half2(lo[2], lo[3]);
}

// Transpose + split W*256 into g_B2; z: 0=Wq 1=Wk 2=Wv 3=Wo
__global__ void convB_kernel(const float* __restrict__ Wq, const float* __restrict__ Wk,
                             const float* __restrict__ Wv, const float* __restrict__ Wo) {
    const float* W = (blockIdx.z == 0) ? Wq : (blockIdx.z == 1) ? Wk
                   : (blockIdx.z == 2) ? Wv : Wo;
    __shared__ float sm[32][33];
    int n0 = blockIdx.x * 32, k0 = blockIdx.y * 32;
    int tx = threadIdx.x, ty = threadIdx.y;   // 32 x 8
#pragma unroll
    for (int j = 0; j < 4; j++)
        sm[ty + j * 8][tx] = W[(size_t)(k0 + ty + j * 8) * D_MODEL + n0 + tx];
    __syncthreads();
#pragma unroll
    for (int j = 0; j < 4; j++) {
        int n = n0 + ty + j * 8, k = k0 + tx;
        float v = sm[tx][ty + j * 8] * 256.0f;
        __half h = __float2half_rn(v);
        __half l = __float2half_rn(v - __half2float(h));
        size_t o = (size_t)(blockIdx.z * 1024 + n) * KE + k;
        g_B2[o] = __hadd(h, l);          // fp16(hi+lo)
        g_B2[o + 1024] = h;              // hi
    }
}

// ---------------------------------------------------------------------------
// fp16 GEMM, extended K=2048: C = A' @ B'^T. Tile 128x128, BK=64, S=3 stages,
// one __syncthreads per kb. 2 CTAs/SM.
// ---------------------------------------------------------------------------
#define PITCH 72                         // 64 + 8 pad (144B rows, 16B aligned)
#define TILE_B (128 * PITCH * 2)         // 18432 B per array
#define STAGE_B (2 * TILE_B)             // A + B = 36864 B per stage

template <bool QKV>
__global__ __launch_bounds__(256, 2) void gemm_mma(float* __restrict__ Cout) {
    extern __shared__ __align__(16) __half sm[];
    const int t = threadIdx.x;
    const int warp = t >> 5, lane = t & 31;
    const int m0 = blockIdx.y * 128, n0 = blockIdx.x * 128;
    const int wm0 = (warp >> 1) * 32;
    const int wn0 = (warp & 1) * 64;

    const __half* Bbase = g_B2 + (QKV ? 0 : (size_t)3072 * KE);
    const uint32_t sbase = smem_u32(sm);

    const int lr = t >> 3, lc = (t & 7) * 8;

    auto issue_stage = [&](int slot, int kb) {
        uint32_t so = sbase + (uint32_t)slot * STAGE_B;
#pragma unroll
        for (int p = 0; p < 4; p++) {
            int row = lr + p * 32;
            uint32_t sofs = ((uint32_t)row * PITCH + lc) * 2;
            cp16(so + sofs,          g_A2 + (size_t)(m0 + row) * KE + kb * 64 + lc);
            cp16(so + TILE_B + sofs, Bbase + (size_t)(n0 + row) * KE + kb * 64 + lc);
        }
        CP_COMMIT();
    };

    float d[2][8][4];
#pragma unroll
    for (int i = 0; i < 2; i++)
#pragma unroll
        for (int j = 0; j < 8; j++)
#pragma unroll
            for (int u = 0; u < 4; u++) d[i][j][u] = 0.f;

    const int arow = wm0 + (lane & 15);
    const int acolq = (lane >> 4) * 8;
    const int brow2 = wn0 + (lane >> 4) * 8 + (lane & 7);
    const int bcol2 = ((lane >> 3) & 1) * 8;

    issue_stage(0, 0);
    issue_stage(1, 1);

    for (int kb = 0; kb < 32; kb++) {
        CP_WAIT(1);
        __syncthreads();
        if (kb + 2 < 32) issue_stage((kb + 2) % 3, kb + 2);
        uint32_t so = sbase + (uint32_t)(kb % 3) * STAGE_B;
#pragma unroll
        for (int ks = 0; ks < 4; ks++) {
            uint32_t a4[2][4];
#pragma unroll
            for (int i = 0; i < 2; i++)
                ldm_x4(a4[i], so + ((uint32_t)(arow + i * 16) * PITCH + ks * 16 + acolq) * 2);
#pragma unroll
            for (int jp = 0; jp < 4; jp++) {
                uint32_t b4[4];
                ldm_x4(b4, so + TILE_B +
                           ((uint32_t)(brow2 + jp * 16) * PITCH + ks * 16 + bcol2) * 2);
#pragma unroll
                for (int i = 0; i < 2; i++) {
                    mma_hf(d[i][2 * jp],     a4[i], b4 + 0);
                    mma_hf(d[i][2 * jp + 1], a4[i], b4 + 2);
                }
            }
        }
    }

    // epilogue (results carry x256 from W scaling)
    const float inv256 = 1.0f / 256.0f;
#pragma unroll
    for (int i = 0; i < 2; i++) {
        int r = m0 + wm0 + i * 16 + (lane >> 2);
#pragma unroll
        for (int j = 0; j < 8; j++) {
            int n = n0 + wn0 + j * 8 + (lane & 3) * 2;
#pragma unroll
            for (int half_ = 0; half_ < 2; half_++) {
                int rr = r + half_ * 8;
                float v0 = d[i][j][2 * half_ + 0] * inv256;
                float v1 = d[i][j][2 * half_ + 1] * inv256;
                if (QKV) {
                    int z = n >> 10, hd = (n >> 6) & 15, dd = n & 63;
                    if (z == 0) {
                        __half* q = g_Q2 + (size_t)hd * HSZ + (size_t)rr * 128 + dd;
                        __half h0 = __float2half_rn(v0), h1 = __float2half_rn(v1);
                        *(__half2*)q = __halves2half2(h0, h1);
                        *(__half2*)(q + 64) = __halves2half2(
                            __float2half_rn(v0 - __half2float(h0)),
                            __float2half_rn(v1 - __half2float(h1)));
                    } else if (z == 1) {
                        __half* k = g_K2 + (size_t)hd * HSZ + (size_t)rr * 128 + dd;
                        __half h0 = __float2half_rn(v0), h1 = __float2half_rn(v1);
                        __half l0 = __float2half_rn(v0 - __half2float(h0));
                        __half l1 = __float2half_rn(v1 - __half2float(h1));
                        *(__half2*)k = __halves2half2(__hadd(h0, l0), __hadd(h1, l1));
                        *(__half2*)(k + 64) = __halves2half2(h0, h1);
                    } else {
                        __half* vv = g_V + (size_t)hd * HSZV + (size_t)rr * 64 + dd;
                        *(__half2*)vv = __halves2half2(__float2half_rn(v0), __float2half_rn(v1));
                    }
                } else {
                    *(float2*)(Cout + (size_t)rr * D_MODEL + n) = make_float2(v0, v1);
                }
            }
        }
    }
}

// ---------------------------------------------------------------------------
// fp16 flash attention. CTA = (head, 128 q). QK^T over d'=128 (extended hi/lo),
// V single fp16. 64-key tiles, S=3 stages, one sync per tile.
// ---------------------------------------------------------------------------
#define PK 136                           // K' pitch (128+8) -> 272B rows
#define PV 72                            // V pitch (64+8)  -> 144B rows, 16B aligned
#define KARR_B (64 * PK * 2)             // 17408
#define VARR_B (64 * PV * 2)             // 9216
#define AST_B  (KARR_B + VARR_B)         // 26624 per stage

__global__ __launch_bounds__(256, 2) void attn_mma() {
    extern __shared__ __align__(16) char smem[];
    const uint32_t sb = smem_u32(smem);
    const int t = threadIdx.x, w = t >> 5, lane = t & 31;
    const int h = blockIdx.y, q0 = blockIdx.x * 128;

    const __half* Q2 = g_Q2 + (size_t)h * HSZ;
    const __half* K2 = g_K2 + (size_t)h * HSZ;
    const __half* Vp = g_V  + (size_t)h * HSZV;

    // ---- stage Q' (128x128) into stage region, extract fragments ----
    {
        int row = t >> 4, colc = (t & 15) * 8;
#pragma unroll
        for (int p = 0; p < 8; p++) {
            int r = row + p * 16;
            cp16(sb + ((uint32_t)r * PK + colc) * 2, Q2 + (size_t)(q0 + r) * 128 + colc);
        }
        CP_COMMIT();
        CP_WAIT(0);
        __syncthreads();
    }
    uint32_t qf[8][4];
    {
        int arow = w * 16 + (lane & 15);
        int acol = (lane >> 4) * 8;
#pragma unroll
        for (int ks = 0; ks < 8; ks++)
            ldm_x4(qf[ks], sb + ((uint32_t)arow * PK + ks * 16 + acol) * 2);
    }
    __syncthreads();

    auto issue_kv = [&](int slot, int i) {
        int k0 = i * 64;
        uint32_t base = sb + (uint32_t)slot * AST_B;
        {
            int row = t >> 4, colc = (t & 15) * 8;
#pragma unroll
            for (int p = 0; p < 4; p++) {
                int r = row + p * 16;
                cp16(base + ((uint32_t)r * PK + colc) * 2, K2 + (size_t)(k0 + r) * 128 + colc);
            }
        }
        {
            int row = t >> 3, colc = (t & 7) * 8;
#pragma unroll
            for (int p = 0; p < 2; p++) {
                int r = row + p * 32;
                cp16(base + KARR_B + ((uint32_t)r * PV + colc) * 2, Vp + (size_t)(k0 + r) * 64 + colc);
            }
        }
        CP_COMMIT();
    };

    issue_kv(0, 0);
    issue_kv(1, 1);

    float o[8][4];
#pragma unroll
    for (int j = 0; j < 8; j++)
#pragma unroll
        for (int u = 0; u < 4; u++) o[j][u] = 0.f;
    float m_r = -1e30f, m_r8 = -1e30f, l_r = 0.f, l_r8 = 0.f;

    const int cq = (lane & 3) * 2;
    const int q_r = q0 + w * 16 + (lane >> 2);
    const float* bh = g_bias + h * 4096 + 2047 - q_r;

    const int k_r = (lane >> 4) * 8 + (lane & 7);
    const int k_c = ((lane >> 3) & 1) * 8;
    const int v_r = (lane & 7) + ((lane >> 3) & 1) * 8;
    const int v_c = (lane >> 4) * 8;

    for (int i = 0; i < 32; i++) {
        CP_WAIT(1);
        __syncthreads();
        if (i + 2 < 32) issue_kv((i + 2) % 3, i + 2);
        uint32_t stb = sb + (uint32_t)(i % 3) * AST_B;
        const int k0 = i * 64;

        // S = Q' K'^T (fp16 extended-d)
        float s[8][4];
#pragma unroll
        for (int j = 0; j < 8; j++)
#pragma unroll
            for (int u = 0; u < 4; u++) s[j][u] = 0.f;
#pragma unroll
        for (int ks = 0; ks < 8; ks++) {
#pragma unroll
            for (int jp = 0; jp < 4; jp++) {
                uint32_t k4[4];
                ldm_x4(k4, stb + ((uint32_t)((jp * 16 + k_r) * PK + ks * 16 + k_c)) * 2);
                mma_hf(s[2 * jp],     qf[ks], k4 + 0);
                mma_hf(s[2 * jp + 1], qf[ks], k4 + 2);
            }
        }

        // bias + online softmax
        float rmax = -1e30f, rmax8 = -1e30f;
#pragma unroll
        for (int j = 0; j < 8; j++) {
            const float* bp = bh + k0 + j * 8 + cq;
            s[j][0] += __ldg(bp);
            s[j][1] += __ldg(bp + 1);
            s[j][2] += __ldg(bp - 8);
            s[j][3] += __ldg(bp - 7);
            rmax  = fmaxf(rmax,  fmaxf(s[j][0], s[j][1]));
            rmax8 = fmaxf(rmax8, fmaxf(s[j][2], s[j][3]));
        }
#pragma unroll
        for (int off = 1; off <= 2; off <<= 1) {
            rmax  = fmaxf(rmax,  __shfl_xor_sync(0xffffffffu, rmax,  off));
            rmax8 = fmaxf(rmax8, __shfl_xor_sync(0xffffffffu, rmax8, off));
        }
        float mn  = fmaxf(m_r,  rmax);
        float mn8 = fmaxf(m_r8, rmax8);
        float cr  = __expf(m_r - mn);
        float cr8 = __expf(m_r8 - mn8);
        m_r = mn; m_r8 = mn8;
        float sum = 0.f, sum8 = 0.f;
#pragma unroll
        for (int j = 0; j < 8; j++) {
            s[j][0] = __expf(s[j][0] - mn);
            s[j][1] = __expf(s[j][1] - mn);
            s[j][2] = __expf(s[j][2] - mn8);
            s[j][3] = __expf(s[j][3] - mn8);
            sum  += s[j][0] + s[j][1];
            sum8 += s[j][2] + s[j][3];
        }
#pragma unroll
        for (int off = 1; off <= 2; off <<= 1) {
            sum  += __shfl_xor_sync(0xffffffffu, sum,  off);
            sum8 += __shfl_xor_sync(0xffffffffu, sum8, off);
        }
        l_r  = l_r  * cr  + sum;
        l_r8 = l_r8 * cr8 + sum8;
#pragma unroll
        for (int j = 0; j < 8; j++) {
            o[j][0] *= cr;  o[j][1] *= cr;
            o[j][2] *= cr8; o[j][3] *= cr8;
        }

        // P (fp16) from fragments
        uint32_t pa[4][4];
#pragma unroll
        for (int ks = 0; ks < 4; ks++) {
            pa[ks][0] = pack_f16(s[2 * ks][0], s[2 * ks][1]);
            pa[ks][1] = pack_f16(s[2 * ks][2], s[2 * ks][3]);
            pa[ks][2] = pack_f16(s[2 * ks + 1][0], s[2 * ks + 1][1]);
            pa[ks][3] = pack_f16(s[2 * ks + 1][2], s[2 * ks + 1][3]);
        }

        // O += P V
#pragma unroll
        for (int ks = 0; ks < 4; ks++) {
#pragma unroll
            for (int jp = 0; jp < 4; jp++) {
                uint32_t v4[4];
                ldm_x4t(v4, stb + KARR_B +
                            ((uint32_t)((ks * 16 + v_r) * PV + jp * 16 + v_c)) * 2);
                mma_hf(o[2 * jp],     pa[ks], v4 + 0);
                mma_hf(o[2 * jp + 1], pa[ks], v4 + 2);
            }
        }
    }

    // epilogue: ctx -> extended-K A' rows (hi | lo) for the out GEMM
    float ir = 1.f / l_r, ir8 = 1.f / l_r8;
#pragma unroll
    for (int j = 0; j < 8; j++) {
        int col = h * 64 + j * 8 + cq;
#pragma unroll
        for (int half_ = 0; half_ < 2; half_++) {
            int rr = q_r + half_ * 8;
            float sc = half_ ? ir8 : ir;
            float v0 = o[j][2 * half_ + 0] * sc;
            float v1 = o[j][2 * half_ + 1] * sc;
            __half h0 = __float2half_rn(v0), h1 = __float2half_rn(v1);
            __half* dst = g_A2 + (size_t)rr * KE + col;
            *(__half2*)dst = __halves2half2(h0, h1);
            *(__half2*)(dst + 1024) = __halves2half2(
                __float2half_rn(v0 - __half2float(h0)),
                __float2half_rn(v1 - __half2float(h1)));
        }
    }
}

// ---------------------------------------------------------------------------
extern "C" void kernel_launch(void* const* d_in, const int* in_sizes, int n_in,
                              void* d_out, int out_size) {
    const float* X   = (const float*)d_in[0];
    const float* Wq  = (const float*)d_in[1];
    const float* Wk  = (const float*)d_in[2];
    const float* Wv  = (const float*)d_in[3];
    const float* Wo  = (const float*)d_in[4];
    const float* rel = (const float*)d_in[5];
    float* out = (float*)d_out;

    const int gemm_smem = 3 * STAGE_B;      // 110592
    const int attn_smem = 3 * AST_B;        // 79872 (>= 34816 Q staging)
    cudaFuncSetAttribute(gemm_mma<true>,  cudaFuncAttributeMaxDynamicSharedMemorySize, gemm_smem);
    cudaFuncSetAttribute(gemm_mma<false>, cudaFuncAttributeMaxDynamicSharedMemorySize, gemm_smem);
    cudaFuncSetAttribute(attn_mma,        cudaFuncAttributeMaxDynamicSharedMemorySize, attn_smem);

    bias_kernel<<<(N_HEADS * 4095 + 255) / 256, 256>>>(rel);
    convA_kernel<<<(S_LEN * D_MODEL / 4) / 256, 256>>>(X);
    convB_kernel<<<dim3(32, 32, 4), dim3(32, 8)>>>(Wq, Wk, Wv, Wo);
    gemm_mma<true><<<dim3(24, 16), 256, gemm_smem>>>(nullptr);
    attn_mma<<<dim3(16, 16), 256, attn_smem>>>();
    gemm_mma<false><<<dim3(8, 16), 256, gemm_smem>>>(out);
}